// round 15
// baseline (speedup 1.0000x reference)
#include <cuda_runtime.h>
#include <cuda_bf16.h>
#include <math.h>
#include <stdint.h>

#define N_NODES 50000
#define N_EDGES 500000
#define C 128
#define G3 384
#define NC (N_NODES*C)
#define M3 (3*N_NODES)
#define FW (C*G3)            // 49152 per fused weight
#define CW (C*C)             // 16384 per conv weight

typedef __nv_bfloat16 bf16;
typedef __nv_bfloat162 bf162;

// ---------------- scratch (device globals) -----------------------------------
__device__ float g_h[NC];
__device__ float g_x[NC];
__device__ bf16  g_hh[NC], g_hl[NC];
__device__ bf16  g_mh[3*NC], g_ml[3*NC];     // per-type GRU state
__device__ bf16  g_ah[3*NC], g_al[3*NC];     // per-type gathered m
// weights
__device__ bf16  g_cwh[18*CW], g_cwl[18*CW];
__device__ bf16  g_wihh[6*G3*C], g_wihl[6*G3*C];
__device__ bf16  g_whhh[6*G3*C], g_whhl[6*G3*C];
__device__ bf16  g_w1h[CW], g_w1l[CW];
__device__ float g_F[18*FW];
__device__ bf16  g_ffh[18*FW], g_ffl[18*FW];
// CSR
__device__ int g_cnt[M3], g_incl[M3], g_cur[M3], g_bsum[256];
__device__ int g_indptr[M3+1];
__device__ int g_eidx[N_EDGES];

// ---------------- helpers ----------------------------------------------------
__device__ __forceinline__ uint32_t smem_u32(const void* p) {
    uint32_t a;
    asm("{ .reg .u64 t; cvta.to.shared.u64 t, %1; cvt.u32.u64 %0, t; }"
        : "=r"(a) : "l"(p));
    return a;
}

#define LDSM4(r, addr) \
    asm volatile("ldmatrix.sync.aligned.m8n8.x4.shared.b16 {%0,%1,%2,%3}, [%4];" \
        : "=r"((r)[0]), "=r"((r)[1]), "=r"((r)[2]), "=r"((r)[3]) : "r"(addr))

#define MMA(d, a, b) \
    asm volatile("mma.sync.aligned.m16n8k16.row.col.f32.bf16.bf16.f32 " \
        "{%0,%1,%2,%3}, {%4,%5,%6,%7}, {%8,%9}, {%0,%1,%2,%3};" \
        : "+f"((d)[0]), "+f"((d)[1]), "+f"((d)[2]), "+f"((d)[3]) \
        : "r"((a)[0]), "r"((a)[1]), "r"((a)[2]), "r"((a)[3]), \
          "r"((b)[0]), "r"((b)[1]))

#define CP_ASYNC16(saddr, gptr) \
    asm volatile("cp.async.cg.shared.global [%0], [%1], 16;" \
        :: "r"(saddr), "l"(gptr))
#define CP_COMMIT() asm volatile("cp.async.commit_group;" ::: "memory")
#define CP_WAIT0()  asm volatile("cp.async.wait_group 0;" ::: "memory")
#define BARG(id)    asm volatile("bar.sync %0, 256;" :: "r"(id) : "memory")

__device__ __forceinline__ void split1(float v, bf16& h, bf16& l) {
    h = __float2bfloat16(v);
    l = __float2bfloat16(v - __bfloat162float(h));
}

__device__ __forceinline__ void acc4(float4& s, uint2 uh, uint2 ul) {
    float2 a = __bfloat1622float2(*(bf162*)&uh.x);
    float2 b = __bfloat1622float2(*(bf162*)&uh.y);
    float2 c = __bfloat1622float2(*(bf162*)&ul.x);
    float2 d = __bfloat1622float2(*(bf162*)&ul.y);
    s.x += a.x + c.x; s.y += a.y + c.y;
    s.z += b.x + d.x; s.w += b.y + d.y;
}

// accumulate 8 channels (uint4 = 8 bf16) hi+lo into fp32
__device__ __forceinline__ void acc8(float* a, uint4 vh, uint4 vl) {
    float2 p;
    p = __bfloat1622float2(*(bf162*)&vh.x); a[0] += p.x; a[1] += p.y;
    p = __bfloat1622float2(*(bf162*)&vh.y); a[2] += p.x; a[3] += p.y;
    p = __bfloat1622float2(*(bf162*)&vh.z); a[4] += p.x; a[5] += p.y;
    p = __bfloat1622float2(*(bf162*)&vh.w); a[6] += p.x; a[7] += p.y;
    p = __bfloat1622float2(*(bf162*)&vl.x); a[0] += p.x; a[1] += p.y;
    p = __bfloat1622float2(*(bf162*)&vl.y); a[2] += p.x; a[3] += p.y;
    p = __bfloat1622float2(*(bf162*)&vl.z); a[4] += p.x; a[5] += p.y;
    p = __bfloat1622float2(*(bf162*)&vl.w); a[6] += p.x; a[7] += p.y;
}

#define TS 136
#define MAT_BYTES (128 * TS * 2)   // 34816
#define HALF_BYTES (64 * TS * 2)   // 17408

// 32m x 32n warp-tile GEMM; B buffer holds 64 n-rows (n0 in {0,32}).
__device__ __forceinline__ void gemm_tile32(uint32_t uAH, uint32_t uAL,
                                            uint32_t uBH, uint32_t uBL,
                                            int m0, int n0, int lane,
                                            float acc[2][4][4]) {
#pragma unroll
    for (int mi = 0; mi < 2; mi++)
#pragma unroll
        for (int nj = 0; nj < 4; nj++)
#pragma unroll
            for (int q = 0; q < 4; q++) acc[mi][nj][q] = 0.f;

    const int arow = lane & 15;
    const int acol = (lane >> 4) << 3;
    const int brow = (lane & 7) + ((lane >> 4) << 3);
    const int bcol = ((lane >> 3) & 1) << 3;

#pragma unroll
    for (int ks = 0; ks < 8; ks++) {
        const int k = ks * 16;
        uint32_t ah[2][4], al[2][4];
#pragma unroll
        for (int mi = 0; mi < 2; mi++) {
            uint32_t off = (uint32_t)(((m0 + mi * 16 + arow) * TS + k + acol) * 2);
            LDSM4(ah[mi], uAH + off);
            LDSM4(al[mi], uAL + off);
        }
        uint32_t bh[4][2], bl[4][2];
#pragma unroll
        for (int nq = 0; nq < 2; nq++) {
            uint32_t off = (uint32_t)(((n0 + nq * 16 + brow) * TS + k + bcol) * 2);
            uint32_t r4[4];
            LDSM4(r4, uBH + off);
            bh[2*nq][0]=r4[0]; bh[2*nq][1]=r4[1]; bh[2*nq+1][0]=r4[2]; bh[2*nq+1][1]=r4[3];
            LDSM4(r4, uBL + off);
            bl[2*nq][0]=r4[0]; bl[2*nq][1]=r4[1]; bl[2*nq+1][0]=r4[2]; bl[2*nq+1][1]=r4[3];
        }
#pragma unroll
        for (int mi = 0; mi < 2; mi++)
#pragma unroll
            for (int nj = 0; nj < 4; nj++) {
                MMA(acc[mi][nj], ah[mi], bh[nj]);
                MMA(acc[mi][nj], ah[mi], bl[nj]);
                MMA(acc[mi][nj], al[mi], bh[nj]);
            }
    }
}

// ---------------- gi/gh GEMM + GRU: 128-row tile, 512 threads ----------------
// Two independent 8-warp groups (named barriers): group g owns output columns
// [64g, 64g+64) of each 128-col block, with its own half-width W buffers.
// SMEM: A1h|A1l|A2h|A2l (4x34816) | W halves (4x17408) = 208896 B.
__global__ void __launch_bounds__(512, 1)
k_gates_b(const bf16* __restrict__ aggmh, const bf16* __restrict__ aggml,
          const bf16* __restrict__ a2hb,  const bf16* __restrict__ a2lb,
          int a2stride,
          const bf16* __restrict__ ffh, const bf16* __restrict__ ffl,
          const bf16* __restrict__ whhhb, const bf16* __restrict__ whhlb,
          const float* __restrict__ bihb, const float* __restrict__ bhhb,
          bf16* __restrict__ mh_out, bf16* __restrict__ ml_out) {
    extern __shared__ char sm[];
    bf16* A1H = (bf16*)(sm);
    bf16* A1L = (bf16*)(sm + MAT_BYTES);
    bf16* A2H = (bf16*)(sm + 2 * MAT_BYTES);
    bf16* A2L = (bf16*)(sm + 3 * MAT_BYTES);
    bf16* WGH[2] = { (bf16*)(sm + 4 * MAT_BYTES),
                     (bf16*)(sm + 4 * MAT_BYTES + 2 * HALF_BYTES) };
    bf16* WGL[2] = { (bf16*)(sm + 4 * MAT_BYTES + HALF_BYTES),
                     (bf16*)(sm + 4 * MAT_BYTES + 3 * HALF_BYTES) };

    const int tid  = threadIdx.x;
    const int wid  = tid >> 5, lane = tid & 31;
    const int grp  = tid >> 8;            // 0 or 1 (warps 0-7 / 8-15)
    const int tg   = tid & 255;           // thread id within group
    const int row0 = blockIdx.x * 128;
    const int t    = blockIdx.y;

    const bf16* A1hG = aggmh + (size_t)t * NC;
    const bf16* A1lG = aggml + (size_t)t * NC;
    const bf16* A2hG = a2hb + (size_t)t * a2stride;
    const bf16* A2lG = a2lb + (size_t)t * a2stride;
    const bf16* BIH = ffh + (size_t)t * 3 * FW;
    const bf16* BIL = ffl + (size_t)t * 3 * FW;
    const bf16* BHH = whhhb + (size_t)t * FW;
    const bf16* BHL = whhlb + (size_t)t * FW;
    const float* bih = bihb + t * G3;
    const float* bhh = bhhb + t * G3;
    bf16* mho = mh_out + (size_t)t * NC;
    bf16* mlo = ml_out + (size_t)t * NC;

    const uint32_t uA1H = smem_u32(A1H), uA1L = smem_u32(A1L);
    const uint32_t uA2H = smem_u32(A2H), uA2L = smem_u32(A2L);
    const uint32_t uWH  = smem_u32(WGH[grp]), uWL = smem_u32(WGL[grp]);
    const int barid = 1 + grp;

#define STAGE_W(srcH_, srcL_, blk_) do { \
    for (int i_ = 0; i_ < 4; i_++) { \
        int g_ = tg + i_ * 256; \
        int n_ = g_ >> 4, k8_ = (g_ & 15) * 8; \
        size_t o_ = (size_t)((blk_) * 128 + grp * 64 + n_) * C + k8_; \
        uint32_t so_ = (uint32_t)((n_ * TS + k8_) * 2); \
        CP_ASYNC16(uWH + so_, (srcH_) + o_); \
        CP_ASYNC16(uWL + so_, (srcL_) + o_); \
    } \
    CP_COMMIT(); \
} while (0)

    STAGE_W(BIH, BIL, 0);

#pragma unroll
    for (int i = 0; i < 4; i++) {
        int g = tid + i * 512;
        int r = g >> 4, k8 = (g & 15) * 8;
        uint4 v1h = make_uint4(0,0,0,0), v1l = v1h, v2h = v1h, v2l = v1h;
        if (row0 + r < N_NODES) {
            size_t o = (size_t)(row0 + r) * C + k8;
            v1h = *(const uint4*)(A1hG + o);
            v1l = *(const uint4*)(A1lG + o);
            v2h = *(const uint4*)(A2hG + o);
            v2l = *(const uint4*)(A2lG + o);
        }
        int so = r * TS + k8;
        *(uint4*)(A1H + so) = v1h;
        *(uint4*)(A1L + so) = v1l;
        *(uint4*)(A2H + so) = v2h;
        *(uint4*)(A2L + so) = v2l;
    }
    CP_WAIT0();
    __syncthreads();

    const int m0 = (wid & 3) * 32;
    const int n0 = ((wid >> 2) & 1) * 32;

    float rg[2][4][4], zg[2][4][4];

#pragma unroll
    for (int blk = 0; blk < 3; blk++) {
        float acc_i[2][4][4], acc_h[2][4][4];
        gemm_tile32(uA1H, uA1L, uWH, uWL, m0, n0, lane, acc_i);
        BARG(barid);
        STAGE_W(BHH, BHL, blk);
        CP_WAIT0();
        BARG(barid);
        gemm_tile32(uA2H, uA2L, uWH, uWL, m0, n0, lane, acc_h);
        BARG(barid);
        if (blk < 2) STAGE_W(BIH, BIL, blk + 1);

        if (blk == 0 || blk == 1) {
#pragma unroll
            for (int mi = 0; mi < 2; mi++)
#pragma unroll
                for (int nj = 0; nj < 4; nj++) {
                    int c = blk * 128 + grp * 64 + n0 + nj * 8 + (lane & 3) * 2;
                    float bi0 = bih[c], bi1 = bih[c + 1];
                    float bh0 = bhh[c], bh1 = bhh[c + 1];
#pragma unroll
                    for (int q = 0; q < 4; q++) {
                        float pre = acc_i[mi][nj][q] + ((q & 1) ? bi1 : bi0)
                                  + acc_h[mi][nj][q] + ((q & 1) ? bh1 : bh0);
                        float gv = 1.f / (1.f + __expf(-pre));
                        if (blk == 0) rg[mi][nj][q] = gv;
                        else          zg[mi][nj][q] = gv;
                    }
                }
        } else {
#pragma unroll
            for (int mi = 0; mi < 2; mi++)
#pragma unroll
                for (int nj = 0; nj < 4; nj++) {
                    int mc = grp * 64 + n0 + nj * 8 + (lane & 3) * 2;
                    int c = 256 + mc;
                    float bi0 = bih[c], bi1 = bih[c + 1];
                    float bh0 = bhh[c], bh1 = bhh[c + 1];
                    float o2[4];
#pragma unroll
                    for (int q = 0; q < 4; q++) {
                        int rl = m0 + mi * 16 + (lane >> 2) + (q >> 1) * 8;
                        int cc = mc + (q & 1);
                        float pi = acc_i[mi][nj][q] + ((q & 1) ? bi1 : bi0);
                        float phv = acc_h[mi][nj][q] + ((q & 1) ? bh1 : bh0);
                        float n = tanhf(pi + rg[mi][nj][q] * phv);
                        float z = zg[mi][nj][q];
                        float mv = __bfloat162float(A2H[rl * TS + cc])
                                 + __bfloat162float(A2L[rl * TS + cc]);
                        o2[q] = (1.f - z) * n + z * mv;
                    }
#pragma unroll
                    for (int h2 = 0; h2 < 2; h2++) {
                        int gr = row0 + m0 + mi * 16 + (lane >> 2) + h2 * 8;
                        if (gr >= N_NODES) continue;
                        float v0 = o2[h2 * 2], v1 = o2[h2 * 2 + 1];
                        bf16 h0, l0, h1, l1;
                        split1(v0, h0, l0); split1(v1, h1, l1);
                        bf162 ph2; ph2.x = h0; ph2.y = h1;
                        bf162 pl2; pl2.x = l0; pl2.y = l1;
                        size_t go = (size_t)gr * C + mc;
                        *(bf162*)(mho + go) = ph2;
                        *(bf162*)(mlo + go) = pl2;
                    }
                }
        }
        if (blk < 2) {
            CP_WAIT0();
            BARG(barid);
        }
    }
#undef STAGE_W
}

// ---------------- F = conv_w @ wih^T -----------------------------------------
__global__ void __launch_bounds__(256, 1)
k_fuse(const bf16* __restrict__ cwh, const bf16* __restrict__ cwl,
       const bf16* __restrict__ wihh, const bf16* __restrict__ wihl,
       float* __restrict__ F) {
    extern __shared__ char sm[];
    bf16* AH = (bf16*)(sm);
    bf16* AL = (bf16*)(sm + MAT_BYTES);
    bf16* BH = (bf16*)(sm + 2 * MAT_BYTES);
    bf16* BL = (bf16*)(sm + 3 * MAT_BYTES);

    const int tid  = threadIdx.x;
    const int col0 = blockIdx.x * 128;
    const int w    = blockIdx.y;
    const int bt   = w / 3;
    const bf16* Ah = cwh + (size_t)w * CW;
    const bf16* Al = cwl + (size_t)w * CW;
    const bf16* Wh = wihh + (size_t)bt * FW + (size_t)col0 * C;
    const bf16* Wl = wihl + (size_t)bt * FW + (size_t)col0 * C;
    float* Y = F + (size_t)w * FW;

#pragma unroll
    for (int i = 0; i < 8; i++) {
        int g = tid + i * 256;
        int r = g >> 4, k8 = (g & 15) * 8;
        *(uint4*)(AH + r * TS + k8) = *(const uint4*)(Ah + (size_t)r * C + k8);
        *(uint4*)(AL + r * TS + k8) = *(const uint4*)(Al + (size_t)r * C + k8);
        *(uint4*)(BH + r * TS + k8) = *(const uint4*)(Wh + (size_t)r * C + k8);
        *(uint4*)(BL + r * TS + k8) = *(const uint4*)(Wl + (size_t)r * C + k8);
    }
    __syncthreads();

    const int wid  = tid >> 5, lane = tid & 31;
    const int m0 = (wid & 3) * 32;
    const int n0 = (wid >> 2) * 64;
    const int arow = lane & 15;
    const int acol = (lane >> 4) << 3;
    const int brow = (lane & 7) + ((lane >> 4) << 3);
    const int bcol = ((lane >> 3) & 1) << 3;
    const uint32_t uAH = smem_u32(AH), uAL = smem_u32(AL);
    const uint32_t uBH = smem_u32(BH), uBL = smem_u32(BL);

    float acc[2][8][4];
#pragma unroll
    for (int mi = 0; mi < 2; mi++)
#pragma unroll
        for (int nj = 0; nj < 8; nj++)
#pragma unroll
            for (int q = 0; q < 4; q++) acc[mi][nj][q] = 0.f;

#pragma unroll
    for (int ks = 0; ks < 8; ks++) {
        const int k = ks * 16;
        uint32_t ah[2][4], al[2][4];
#pragma unroll
        for (int mi = 0; mi < 2; mi++) {
            uint32_t off = (uint32_t)(((m0 + mi * 16 + arow) * TS + k + acol) * 2);
            LDSM4(ah[mi], uAH + off);
            LDSM4(al[mi], uAL + off);
        }
        uint32_t bh[8][2], bl[8][2];
#pragma unroll
        for (int nq = 0; nq < 4; nq++) {
            uint32_t off = (uint32_t)(((n0 + nq * 16 + brow) * TS + k + bcol) * 2);
            uint32_t r4[4];
            LDSM4(r4, uBH + off);
            bh[2*nq][0]=r4[0]; bh[2*nq][1]=r4[1]; bh[2*nq+1][0]=r4[2]; bh[2*nq+1][1]=r4[3];
            LDSM4(r4, uBL + off);
            bl[2*nq][0]=r4[0]; bl[2*nq][1]=r4[1]; bl[2*nq+1][0]=r4[2]; bl[2*nq+1][1]=r4[3];
        }
#pragma unroll
        for (int mi = 0; mi < 2; mi++)
#pragma unroll
            for (int nj = 0; nj < 8; nj++) {
                MMA(acc[mi][nj], ah[mi], bh[nj]);
                MMA(acc[mi][nj], ah[mi], bl[nj]);
                MMA(acc[mi][nj], al[mi], bh[nj]);
            }
    }

    const int rbase = m0 + (lane >> 2);
    const int cbase = n0 + (lane & 3) * 2;
#pragma unroll
    for (int mi = 0; mi < 2; mi++)
#pragma unroll
        for (int nj = 0; nj < 8; nj++) {
            int gr = rbase + mi * 16;
            int gc = col0 + cbase + nj * 8;
            *(float2*)(Y + (size_t)gr * G3 + gc) =
                make_float2(acc[mi][nj][0], acc[mi][nj][1]);
            *(float2*)(Y + (size_t)(gr + 8) * G3 + gc) =
                make_float2(acc[mi][nj][2], acc[mi][nj][3]);
        }
}

// F [w][k][n] -> Ff [w][n][k] hi/lo
__global__ void k_cvt_trF(const float* __restrict__ F, bf16* __restrict__ oh,
                          bf16* __restrict__ ol) {
    int idx = blockIdx.x * 256 + threadIdx.x;
    if (idx >= 18 * FW) return;
    int w = idx / FW, r = idx % FW;
    int n = r >> 7, k = r & 127;
    float v = F[(size_t)w * FW + (size_t)k * G3 + n];
    bf16 h, l; split1(v, h, l);
    oh[idx] = h; ol[idx] = l;
}

// ---------------- fused weight split (all weight tensors, one launch) --------
__global__ void k_cvtall(const float* __restrict__ cw, const float* __restrict__ wih,
                         const float* __restrict__ whh, const float* __restrict__ w1,
                         bf16* __restrict__ cwh, bf16* __restrict__ cwl,
                         bf16* __restrict__ wihh, bf16* __restrict__ wihl,
                         bf16* __restrict__ whhh, bf16* __restrict__ whhl,
                         bf16* __restrict__ w1h, bf16* __restrict__ w1l) {
    int i = blockIdx.x * 256 + threadIdx.x;
    const int n1 = 18 * CW;
    const int n2 = 6 * G3 * C;
    bf16 h, l;
    if (i < n1) {
        split1(cw[i], h, l); cwh[i] = h; cwl[i] = l; return;
    }
    i -= n1;
    if (i < n2) {
        split1(wih[i], h, l); wihh[i] = h; wihl[i] = l; return;
    }
    i -= n2;
    if (i < n2) {
        split1(whh[i], h, l); whhh[i] = h; whhl[i] = l; return;
    }
    i -= n2;
    if (i < CW) {
        split1(w1[i], h, l); w1h[i] = h; w1l[i] = l;
    }
}

// ---------------- CSR build --------------------------------------------------
__global__ void k_izero2(int* __restrict__ a, int* __restrict__ b, int n) {
    int i = blockIdx.x * 256 + threadIdx.x;
    if (i < n) { a[i] = 0; b[i] = 0; }
}
__global__ void k_count(const int* __restrict__ ei, const int* __restrict__ et,
                        int* __restrict__ cnt) {
    int e = blockIdx.x * 256 + threadIdx.x;
    if (e >= N_EDGES) return;
    atomicAdd(cnt + et[e] * N_NODES + ei[N_EDGES + e], 1);
}
__global__ void k_scan1(const int* __restrict__ cnt, int* __restrict__ incl,
                        int* __restrict__ bsum) {
    __shared__ int sm[1024];
    int i = blockIdx.x * 1024 + threadIdx.x;
    int v = (i < M3) ? cnt[i] : 0;
    sm[threadIdx.x] = v;
    __syncthreads();
#pragma unroll
    for (int off = 1; off < 1024; off <<= 1) {
        int t = (threadIdx.x >= off) ? sm[threadIdx.x - off] : 0;
        __syncthreads();
        sm[threadIdx.x] += t;
        __syncthreads();
    }
    if (i < M3) incl[i] = sm[threadIdx.x];
    if (threadIdx.x == 1023) bsum[blockIdx.x] = sm[1023];
}
// parallel exclusive scan of block sums (nb <= 256)
__global__ void k_scan2(int* __restrict__ bsum, int nb) {
    __shared__ int sm2[256];
    int i = threadIdx.x;
    int v = (i < nb) ? bsum[i] : 0;
    sm2[i] = v;
    __syncthreads();
#pragma unroll
    for (int off = 1; off < 256; off <<= 1) {
        int t = (i >= off) ? sm2[i - off] : 0;
        __syncthreads();
        sm2[i] += t;
        __syncthreads();
    }
    if (i < nb) bsum[i] = sm2[i] - v;   // exclusive prefix
}
__global__ void k_scan3(const int* __restrict__ incl, const int* __restrict__ bsum,
                        int* __restrict__ indptr) {
    int i = blockIdx.x * 1024 + threadIdx.x;
    if (i < M3) indptr[i + 1] = incl[i] + bsum[blockIdx.x];
    if (i == 0) indptr[0] = 0;
}
// fill using indptr base + zeroed per-bucket counter
__global__ void k_fill(const int* __restrict__ ei, const int* __restrict__ et,
                       const int* __restrict__ indptr, int* __restrict__ cur,
                       int* __restrict__ eidx) {
    int e = blockIdx.x * 256 + threadIdx.x;
    if (e >= N_EDGES) return;
    int tn = et[e] * N_NODES + ei[N_EDGES + e];
    int p = indptr[tn] + atomicAdd(cur + tn, 1);
    eidx[p] = ei[e];
}

// ---------------- gather: 1 node/warp, half-warps split edges ----------------
// Each half-warp (16 lanes x 8 channels = full 128 channels) processes the
// even/odd half of the node's edge list -> chain length ~degree/2. Partials
// combined via shfl_xor(16) before split/store.
__global__ void k_gather3(const bf16* __restrict__ srch, const bf16* __restrict__ srcl,
                          int sstride,
                          const int* __restrict__ eidx, const int* __restrict__ indptr,
                          bf16* __restrict__ aggh, bf16* __restrict__ aggl) {
    int node = blockIdx.x * 8 + (threadIdx.x >> 5);
    int half = (threadIdx.x >> 4) & 1;
    int lane16 = threadIdx.x & 15;
    int t = blockIdx.y;
    if (node >= N_NODES) return;
    const bf16* mh = srch + (size_t)t * sstride;
    const bf16* ml = srcl + (size_t)t * sstride;
    int tn = t * N_NODES + node;
    int beg = indptr[tn], end = indptr[tn + 1];
    float a[8];
#pragma unroll
    for (int q = 0; q < 8; q++) a[q] = 0.f;
    const int co = lane16 * 8;
    for (int j = beg + half; j < end; j += 2) {
        size_t o = (size_t)eidx[j] * C + co;
        uint4 vh = *(const uint4*)(mh + o);
        uint4 vl = *(const uint4*)(ml + o);
        acc8(a, vh, vl);
    }
    // combine half-warp partials (all 32 lanes converged here)
#pragma unroll
    for (int q = 0; q < 8; q++)
        a[q] += __shfl_xor_sync(0xffffffffu, a[q], 16);
    if (half == 0) {
        unsigned hs[8], ls[8];
#pragma unroll
        for (int q = 0; q < 8; q++) {
            bf16 h, l; split1(a[q], h, l);
            hs[q] = (unsigned)__bfloat16_as_ushort(h);
            ls[q] = (unsigned)__bfloat16_as_ushort(l);
        }
        uint4 oh, ol;
        oh.x = hs[0] | (hs[1] << 16); oh.y = hs[2] | (hs[3] << 16);
        oh.z = hs[4] | (hs[5] << 16); oh.w = hs[6] | (hs[7] << 16);
        ol.x = ls[0] | (ls[1] << 16); ol.y = ls[2] | (ls[3] << 16);
        ol.z = ls[4] | (ls[5] << 16); ol.w = ls[6] | (ls[7] << 16);
        size_t o = (size_t)t * NC + (size_t)node * C + co;
        *(uint4*)(aggh + o) = oh;
        *(uint4*)(aggl + o) = ol;
    }
}

// ---------------- head GEMM (128-row tile) -----------------------------------
__global__ void __launch_bounds__(256, 1)
k_mma2(const bf16* __restrict__ Ah, const bf16* __restrict__ Al,
       const bf16* __restrict__ Wh, const bf16* __restrict__ Wl,
       const float* __restrict__ bias, float* __restrict__ Y) {
    extern __shared__ char sm[];
    bf16* AH = (bf16*)(sm);
    bf16* AL = (bf16*)(sm + MAT_BYTES);
    bf16* BH = (bf16*)(sm + 2 * MAT_BYTES);
    bf16* BL = (bf16*)(sm + 3 * MAT_BYTES);

    const int tid  = threadIdx.x;
    const int row0 = blockIdx.x * 128;

#pragma unroll
    for (int i = 0; i < 8; i++) {
        int g = tid + i * 256;
        int r = g >> 4, k8 = (g & 15) * 8;
        uint4 vh = make_uint4(0u, 0u, 0u, 0u), vl = vh;
        if (row0 + r < N_NODES) {
            vh = *(const uint4*)(Ah + (size_t)(row0 + r) * C + k8);
            vl = *(const uint4*)(Al + (size_t)(row0 + r) * C + k8);
        }
        *(uint4*)(AH + r * TS + k8) = vh;
        *(uint4*)(AL + r * TS + k8) = vl;
        *(uint4*)(BH + r * TS + k8) = *(const uint4*)(Wh + (size_t)r * C + k8);
        *(uint4*)(BL + r * TS + k8) = *(const uint4*)(Wl + (size_t)r * C + k8);
    }
    __syncthreads();

    const int wid  = tid >> 5, lane = tid & 31;
    const int m0 = (wid & 3) * 32;
    const int n0 = (wid >> 2) * 64;
    const int arow = lane & 15;
    const int acol = (lane >> 4) << 3;
    const int brow = (lane & 7) + ((lane >> 4) << 3);
    const int bcol = ((lane >> 3) & 1) << 3;
    const uint32_t uAH = smem_u32(AH), uAL = smem_u32(AL);
    const uint32_t uBH = smem_u32(BH), uBL = smem_u32(BL);

    float acc[2][8][4];
#pragma unroll
    for (int mi = 0; mi < 2; mi++)
#pragma unroll
        for (int nj = 0; nj < 8; nj++)
#pragma unroll
            for (int q = 0; q < 4; q++) acc[mi][nj][q] = 0.f;

#pragma unroll
    for (int ks = 0; ks < 8; ks++) {
        const int k = ks * 16;
        uint32_t ah[2][4], al[2][4];
#pragma unroll
        for (int mi = 0; mi < 2; mi++) {
            uint32_t off = (uint32_t)(((m0 + mi * 16 + arow) * TS + k + acol) * 2);
            LDSM4(ah[mi], uAH + off);
            LDSM4(al[mi], uAL + off);
        }
        uint32_t bh[8][2], bl[8][2];
#pragma unroll
        for (int nq = 0; nq < 4; nq++) {
            uint32_t off = (uint32_t)(((n0 + nq * 16 + brow) * TS + k + bcol) * 2);
            uint32_t r4[4];
            LDSM4(r4, uBH + off);
            bh[2*nq][0]=r4[0]; bh[2*nq][1]=r4[1]; bh[2*nq+1][0]=r4[2]; bh[2*nq+1][1]=r4[3];
            LDSM4(r4, uBL + off);
            bl[2*nq][0]=r4[0]; bl[2*nq][1]=r4[1]; bl[2*nq+1][0]=r4[2]; bl[2*nq+1][1]=r4[3];
        }
#pragma unroll
        for (int mi = 0; mi < 2; mi++)
#pragma unroll
            for (int nj = 0; nj < 8; nj++) {
                MMA(acc[mi][nj], ah[mi], bh[nj]);
                MMA(acc[mi][nj], ah[mi], bl[nj]);
                MMA(acc[mi][nj], al[mi], bh[nj]);
            }
    }

    const int rbase = row0 + m0 + (lane >> 2);
    const int cbase = n0 + (lane & 3) * 2;
#pragma unroll
    for (int mi = 0; mi < 2; mi++)
#pragma unroll
        for (int nj = 0; nj < 8; nj++) {
            int gr = rbase + mi * 16;
            int gc = cbase + nj * 8;
            float b0 = bias[gc], b1 = bias[gc + 1];
            float2 v0, v1;
            v0.x = fmaxf(acc[mi][nj][0] + b0, 0.f);
            v0.y = fmaxf(acc[mi][nj][1] + b1, 0.f);
            v1.x = fmaxf(acc[mi][nj][2] + b0, 0.f);
            v1.y = fmaxf(acc[mi][nj][3] + b1, 0.f);
            if (gr < N_NODES)
                *(float2*)(Y + (size_t)gr * C + gc) = v0;
            if (gr + 8 < N_NODES)
                *(float2*)(Y + (size_t)(gr + 8) * C + gc) = v1;
        }
}

// ---------------- feature build ----------------------------------------------
__global__ void k_feat(const int* __restrict__ xt, const int* __restrict__ xk,
                       const float* __restrict__ xs, float* __restrict__ h,
                       bf16* __restrict__ hh, bf16* __restrict__ hl) {
    int i = blockIdx.x;
    int c = threadIdx.x;
    int t = xt[i];
    int k = xk[i];
    k = min(max(k, 0), 93);
    float v;
    if (c < 32)       v = (c == t) ? 1.f : 0.f;
    else if (c < 126) v = ((c - 32) == k) ? 1.f : 0.f;
    else              v = xs[i * 2 + (c - 126)];
    size_t o = (size_t)i * C + c;
    h[o] = v;
    bf16 bh, bl; split1(v, bh, bl);
    hh[o] = bh; hl[o] = bl;
}

// ---------------- LayerNorm(h + sum_t m_t)*g+b, ReLU -------------------------
__global__ void k_ln(float* __restrict__ h, const bf16* __restrict__ mh,
                     const bf16* __restrict__ ml,
                     const float* __restrict__ g, const float* __restrict__ b,
                     bf16* __restrict__ hh, bf16* __restrict__ hl) {
    int i = blockIdx.x * 8 + (threadIdx.x >> 5);
    int lane = threadIdx.x & 31;
    if (i >= N_NODES) return;
    size_t o4 = (size_t)i * C + lane * 4;
    float4 v = ((float4*)(h + (size_t)i * C))[lane];
#pragma unroll
    for (int t = 0; t < 3; t++) {
        size_t o = (size_t)t * NC + o4;
        uint2 uh = *(const uint2*)(mh + o);
        uint2 ul = *(const uint2*)(ml + o);
        float4 tmp = make_float4(0.f, 0.f, 0.f, 0.f);
        acc4(tmp, uh, ul);
        v.x += tmp.x; v.y += tmp.y; v.z += tmp.z; v.w += tmp.w;
    }
    float s  = v.x + v.y + v.z + v.w;
    float ss = v.x * v.x + v.y * v.y + v.z * v.z + v.w * v.w;
#pragma unroll
    for (int off = 16; off; off >>= 1) {
        s  += __shfl_xor_sync(0xffffffffu, s, off);
        ss += __shfl_xor_sync(0xffffffffu, ss, off);
    }
    float mu  = s * (1.f / 128.f);
    float var = ss * (1.f / 128.f) - mu * mu;
    float inv = rsqrtf(var + 1e-5f);
    float4 gg = ((const float4*)g)[lane];
    float4 bb = ((const float4*)b)[lane];
    float4 o;
    o.x = fmaxf((v.x - mu) * inv * gg.x + bb.x, 0.f);
    o.y = fmaxf((v.y - mu) * inv * gg.y + bb.y, 0.f);
    o.z = fmaxf((v.z - mu) * inv * gg.z + bb.z, 0.f);
    o.w = fmaxf((v.w - mu) * inv * gg.w + bb.w, 0.f);
    ((float4*)(h + (size_t)i * C))[lane] = o;
    bf16 hx, lx, hy, ly, hz, lz, hw, lw;
    split1(o.x, hx, lx); split1(o.y, hy, ly);
    split1(o.z, hz, lz); split1(o.w, hw, lw);
    bf162 p01, p23, q01, q23;
    p01.x = hx; p01.y = hy; p23.x = hz; p23.y = hw;
    q01.x = lx; q01.y = ly; q23.x = lz; q23.y = lw;
    *(bf162*)(hh + o4)     = p01;
    *(bf162*)(hh + o4 + 2) = p23;
    *(bf162*)(hl + o4)     = q01;
    *(bf162*)(hl + o4 + 2) = q23;
}

// ---------------- head second layer ------------------------------------------
__global__ void k_head2(const float* __restrict__ z, const float* __restrict__ w2,
                        const float* __restrict__ b2, float* __restrict__ out) {
    int i = blockIdx.x * 8 + (threadIdx.x >> 5);
    int lane = threadIdx.x & 31;
    if (i >= N_NODES) return;
    float4 zv = ((const float4*)(z + (size_t)i * C))[lane];
    float4 w0 = ((const float4*)w2)[lane];
    float4 w1 = ((const float4*)(w2 + C))[lane];
    float d0 = zv.x * w0.x + zv.y * w0.y + zv.z * w0.z + zv.w * w0.w;
    float d1 = zv.x * w1.x + zv.y * w1.y + zv.z * w1.z + zv.w * w1.w;
#pragma unroll
    for (int off = 16; off; off >>= 1) {
        d0 += __shfl_xor_sync(0xffffffffu, d0, off);
        d1 += __shfl_xor_sync(0xffffffffu, d1, off);
    }
    if (lane == 0) {
        out[(size_t)i * 2 + 0] = d0 + b2[0];
        out[(size_t)i * 2 + 1] = d1 + b2[1];
    }
}

// ---------------- driver -----------------------------------------------------
extern "C" void kernel_launch(void* const* d_in, const int* in_sizes, int n_in,
                              void* d_out, int out_size) {
    const int*   x_type     = (const int*)d_in[0];
    const int*   x_tok      = (const int*)d_in[1];
    const float* x_small    = (const float*)d_in[2];
    const int*   edge_index = (const int*)d_in[3];
    const int*   edge_type  = (const int*)d_in[4];
    const float* conv_w     = (const float*)d_in[5];
    const float* gru_wih    = (const float*)d_in[6];
    const float* gru_whh    = (const float*)d_in[7];
    const float* gru_bih    = (const float*)d_in[8];
    const float* gru_bhh    = (const float*)d_in[9];
    const float* ln_g       = (const float*)d_in[10];
    const float* ln_b       = (const float*)d_in[11];
    const float* head_w1    = (const float*)d_in[12];
    const float* head_b1    = (const float*)d_in[13];
    const float* head_w2    = (const float*)d_in[14];
    const float* head_b2    = (const float*)d_in[15];
    float* out = (float*)d_out;

    float *ph, *px, *pF;
    bf16 *phh, *phl, *pmh, *pml, *pah, *pal;
    bf16 *pcwh, *pcwl, *pwihh, *pwihl, *pwhhh, *pwhhl, *pw1h, *pw1l, *pffh, *pffl;
    int *pcnt, *pincl, *pcur, *pbsum, *pindptr, *peidx;
    cudaGetSymbolAddress((void**)&ph,   g_h);
    cudaGetSymbolAddress((void**)&px,   g_x);
    cudaGetSymbolAddress((void**)&pF,   g_F);
    cudaGetSymbolAddress((void**)&phh,  g_hh);
    cudaGetSymbolAddress((void**)&phl,  g_hl);
    cudaGetSymbolAddress((void**)&pmh,  g_mh);
    cudaGetSymbolAddress((void**)&pml,  g_ml);
    cudaGetSymbolAddress((void**)&pah,  g_ah);
    cudaGetSymbolAddress((void**)&pal,  g_al);
    cudaGetSymbolAddress((void**)&pcwh, g_cwh);
    cudaGetSymbolAddress((void**)&pcwl, g_cwl);
    cudaGetSymbolAddress((void**)&pwihh, g_wihh);
    cudaGetSymbolAddress((void**)&pwihl, g_wihl);
    cudaGetSymbolAddress((void**)&pwhhh, g_whhh);
    cudaGetSymbolAddress((void**)&pwhhl, g_whhl);
    cudaGetSymbolAddress((void**)&pw1h, g_w1h);
    cudaGetSymbolAddress((void**)&pw1l, g_w1l);
    cudaGetSymbolAddress((void**)&pffh, g_ffh);
    cudaGetSymbolAddress((void**)&pffl, g_ffl);
    cudaGetSymbolAddress((void**)&pcnt, g_cnt);
    cudaGetSymbolAddress((void**)&pincl, g_incl);
    cudaGetSymbolAddress((void**)&pcur, g_cur);
    cudaGetSymbolAddress((void**)&pbsum, g_bsum);
    cudaGetSymbolAddress((void**)&pindptr, g_indptr);
    cudaGetSymbolAddress((void**)&peidx, g_eidx);

    const int SMEMSZ = 4 * MAT_BYTES;                     // 139264 (k_fuse, head)
    const int GSMEM  = 6 * MAT_BYTES;                     // 208896 (gates)
    cudaFuncSetAttribute(k_fuse,
                         cudaFuncAttributeMaxDynamicSharedMemorySize, SMEMSZ);
    cudaFuncSetAttribute(k_mma2,
                         cudaFuncAttributeMaxDynamicSharedMemorySize, SMEMSZ);
    cudaFuncSetAttribute(k_gates_b,
                         cudaFuncAttributeMaxDynamicSharedMemorySize, GSMEM);

    const int rowBlocks = (N_NODES + 127) / 128;    // 391
    const int warpGrid = (N_NODES + 7) / 8;         // 6250 (1 node/warp)
    const int SCANB = (M3 + 1023) / 1024;           // 147
    const int EG = (N_EDGES + 255) / 256;
    const int CVTN = 18 * CW + 2 * 6 * G3 * C + CW; // 901120

    // ---- one-time: features, weight splits, CSR, fused weights ----
    k_feat<<<N_NODES, 128>>>(x_type, x_tok, x_small, ph, phh, phl);
    k_cvtall<<<(CVTN + 255) / 256, 256>>>(conv_w, gru_wih, gru_whh, head_w1,
                                          pcwh, pcwl, pwihh, pwihl,
                                          pwhhh, pwhhl, pw1h, pw1l);

    k_izero2<<<(M3 + 255)/256, 256>>>(pcnt, pcur, M3);
    k_count<<<EG, 256>>>(edge_index, edge_type, pcnt);
    k_scan1<<<SCANB, 1024>>>(pcnt, pincl, pbsum);
    k_scan2<<<1, 256>>>(pbsum, SCANB);
    k_scan3<<<SCANB, 1024>>>(pincl, pbsum, pindptr);
    k_fill<<<EG, 256>>>(edge_index, edge_type, pindptr, pcur, peidx);

    k_fuse<<<dim3(3, 18), 256, SMEMSZ>>>(pcwh, pcwl, pwihh, pwihl, pF);
    k_cvt_trF<<<(18*FW + 255)/256, 256>>>(pF, pffh, pffl);

    for (int b = 0; b < 2; b++) {
        for (int s = 0; s < 3; s++) {
            const bf16* srch = (s == 0) ? phh : pmh;
            const bf16* srcl = (s == 0) ? phl : pml;
            int stride = (s == 0) ? 0 : NC;
            k_gather3<<<dim3(warpGrid, 3), 256>>>(srch, srcl, stride,
                                                  peidx, pindptr, pah, pal);
            k_gates_b<<<dim3(rowBlocks, 3), 512, GSMEM>>>(
                pah, pal, srch, srcl, stride,
                pffh + (size_t)(b * 9 + s) * FW, pffl + (size_t)(b * 9 + s) * FW,
                pwhhh + (size_t)b * 3 * FW, pwhhl + (size_t)b * 3 * FW,
                gru_bih + (size_t)b * 3 * G3, gru_bhh + (size_t)b * 3 * G3,
                pmh, pml);
        }
        k_ln<<<warpGrid, 256>>>(ph, pmh, pml, ln_g + b * C, ln_b + b * C, phh, phl);
    }

    // head
    k_mma2<<<rowBlocks, 256, SMEMSZ>>>(phh, phl, pw1h, pw1l, head_b1, px);
    k_head2<<<warpGrid, 256>>>(px, head_w2, head_b2, out);
}

// round 16
// speedup vs baseline: 1.0358x; 1.0358x over previous
#include <cuda_runtime.h>
#include <cuda_bf16.h>
#include <math.h>
#include <stdint.h>

#define N_NODES 50000
#define N_EDGES 500000
#define C 128
#define G3 384
#define NC (N_NODES*C)
#define M3 (3*N_NODES)
#define FW (C*G3)            // 49152 per fused weight
#define CW (C*C)             // 16384 per conv weight

typedef __nv_bfloat16 bf16;
typedef __nv_bfloat162 bf162;

// ---------------- scratch (device globals) -----------------------------------
__device__ float g_h[NC];
__device__ float g_x[NC];
__device__ bf16  g_hh[NC], g_hl[NC];
__device__ bf16  g_mh[3*NC], g_ml[3*NC];     // per-type GRU state
__device__ bf16  g_ah[3*NC], g_al[3*NC];     // per-type gathered m
// weights
__device__ bf16  g_cwh[18*CW], g_cwl[18*CW];
__device__ bf16  g_wihh[6*G3*C], g_wihl[6*G3*C];
__device__ bf16  g_whhh[6*G3*C], g_whhl[6*G3*C];
__device__ bf16  g_w1h[CW], g_w1l[CW];
__device__ float g_F[18*FW];
__device__ bf16  g_ffh[18*FW], g_ffl[18*FW];
// CSR
__device__ int g_cnt[M3], g_incl[M3], g_cur[M3], g_bsum[256];
__device__ int g_indptr[M3+1];
__device__ int g_eidx[N_EDGES];

// ---------------- helpers ----------------------------------------------------
__device__ __forceinline__ uint32_t smem_u32(const void* p) {
    uint32_t a;
    asm("{ .reg .u64 t; cvta.to.shared.u64 t, %1; cvt.u32.u64 %0, t; }"
        : "=r"(a) : "l"(p));
    return a;
}

#define LDSM4(r, addr) \
    asm volatile("ldmatrix.sync.aligned.m8n8.x4.shared.b16 {%0,%1,%2,%3}, [%4];" \
        : "=r"((r)[0]), "=r"((r)[1]), "=r"((r)[2]), "=r"((r)[3]) : "r"(addr))

#define MMA(d, a, b) \
    asm volatile("mma.sync.aligned.m16n8k16.row.col.f32.bf16.bf16.f32 " \
        "{%0,%1,%2,%3}, {%4,%5,%6,%7}, {%8,%9}, {%0,%1,%2,%3};" \
        : "+f"((d)[0]), "+f"((d)[1]), "+f"((d)[2]), "+f"((d)[3]) \
        : "r"((a)[0]), "r"((a)[1]), "r"((a)[2]), "r"((a)[3]), \
          "r"((b)[0]), "r"((b)[1]))

#define CP_ASYNC16(saddr, gptr) \
    asm volatile("cp.async.cg.shared.global [%0], [%1], 16;" \
        :: "r"(saddr), "l"(gptr))
#define CP_COMMIT() asm volatile("cp.async.commit_group;" ::: "memory")
#define CP_WAIT0()  asm volatile("cp.async.wait_group 0;" ::: "memory")
#define BARG(id)    asm volatile("bar.sync %0, 256;" :: "r"(id) : "memory")

__device__ __forceinline__ void split1(float v, bf16& h, bf16& l) {
    h = __float2bfloat16(v);
    l = __float2bfloat16(v - __bfloat162float(h));
}

__device__ __forceinline__ void acc4(float4& s, uint2 uh, uint2 ul) {
    float2 a = __bfloat1622float2(*(bf162*)&uh.x);
    float2 b = __bfloat1622float2(*(bf162*)&uh.y);
    float2 c = __bfloat1622float2(*(bf162*)&ul.x);
    float2 d = __bfloat1622float2(*(bf162*)&ul.y);
    s.x += a.x + c.x; s.y += a.y + c.y;
    s.z += b.x + d.x; s.w += b.y + d.y;
}

// accumulate 8 channels (uint4 = 8 bf16) hi+lo into fp32
__device__ __forceinline__ void acc8(float* a, uint4 vh, uint4 vl) {
    float2 p;
    p = __bfloat1622float2(*(bf162*)&vh.x); a[0] += p.x; a[1] += p.y;
    p = __bfloat1622float2(*(bf162*)&vh.y); a[2] += p.x; a[3] += p.y;
    p = __bfloat1622float2(*(bf162*)&vh.z); a[4] += p.x; a[5] += p.y;
    p = __bfloat1622float2(*(bf162*)&vh.w); a[6] += p.x; a[7] += p.y;
    p = __bfloat1622float2(*(bf162*)&vl.x); a[0] += p.x; a[1] += p.y;
    p = __bfloat1622float2(*(bf162*)&vl.y); a[2] += p.x; a[3] += p.y;
    p = __bfloat1622float2(*(bf162*)&vl.z); a[4] += p.x; a[5] += p.y;
    p = __bfloat1622float2(*(bf162*)&vl.w); a[6] += p.x; a[7] += p.y;
}

#define TS 136
#define MAT_BYTES (128 * TS * 2)   // 34816
#define HALF_BYTES (64 * TS * 2)   // 17408

// 32m x 32n warp-tile GEMM; B buffer holds 64 n-rows (n0 in {0,32}).
__device__ __forceinline__ void gemm_tile32(uint32_t uAH, uint32_t uAL,
                                            uint32_t uBH, uint32_t uBL,
                                            int m0, int n0, int lane,
                                            float acc[2][4][4]) {
#pragma unroll
    for (int mi = 0; mi < 2; mi++)
#pragma unroll
        for (int nj = 0; nj < 4; nj++)
#pragma unroll
            for (int q = 0; q < 4; q++) acc[mi][nj][q] = 0.f;

    const int arow = lane & 15;
    const int acol = (lane >> 4) << 3;
    const int brow = (lane & 7) + ((lane >> 4) << 3);
    const int bcol = ((lane >> 3) & 1) << 3;

#pragma unroll
    for (int ks = 0; ks < 8; ks++) {
        const int k = ks * 16;
        uint32_t ah[2][4], al[2][4];
#pragma unroll
        for (int mi = 0; mi < 2; mi++) {
            uint32_t off = (uint32_t)(((m0 + mi * 16 + arow) * TS + k + acol) * 2);
            LDSM4(ah[mi], uAH + off);
            LDSM4(al[mi], uAL + off);
        }
        uint32_t bh[4][2], bl[4][2];
#pragma unroll
        for (int nq = 0; nq < 2; nq++) {
            uint32_t off = (uint32_t)(((n0 + nq * 16 + brow) * TS + k + bcol) * 2);
            uint32_t r4[4];
            LDSM4(r4, uBH + off);
            bh[2*nq][0]=r4[0]; bh[2*nq][1]=r4[1]; bh[2*nq+1][0]=r4[2]; bh[2*nq+1][1]=r4[3];
            LDSM4(r4, uBL + off);
            bl[2*nq][0]=r4[0]; bl[2*nq][1]=r4[1]; bl[2*nq+1][0]=r4[2]; bl[2*nq+1][1]=r4[3];
        }
#pragma unroll
        for (int mi = 0; mi < 2; mi++)
#pragma unroll
            for (int nj = 0; nj < 4; nj++) {
                MMA(acc[mi][nj], ah[mi], bh[nj]);
                MMA(acc[mi][nj], ah[mi], bl[nj]);
                MMA(acc[mi][nj], al[mi], bh[nj]);
            }
    }
}

// ---------------- gi/gh GEMM + GRU: 128-row tile, 512 threads ----------------
// Two independent 8-warp groups (named barriers): group g owns output columns
// [64g, 64g+64) of each 128-col block, with its own half-width W buffers.
// SMEM: A1h|A1l|A2h|A2l (4x34816) | W halves (4x17408) = 208896 B.
__global__ void __launch_bounds__(512, 1)
k_gates_b(const bf16* __restrict__ aggmh, const bf16* __restrict__ aggml,
          const bf16* __restrict__ a2hb,  const bf16* __restrict__ a2lb,
          int a2stride,
          const bf16* __restrict__ ffh, const bf16* __restrict__ ffl,
          const bf16* __restrict__ whhhb, const bf16* __restrict__ whhlb,
          const float* __restrict__ bihb, const float* __restrict__ bhhb,
          bf16* __restrict__ mh_out, bf16* __restrict__ ml_out) {
    extern __shared__ char sm[];
    bf16* A1H = (bf16*)(sm);
    bf16* A1L = (bf16*)(sm + MAT_BYTES);
    bf16* A2H = (bf16*)(sm + 2 * MAT_BYTES);
    bf16* A2L = (bf16*)(sm + 3 * MAT_BYTES);
    bf16* WGH[2] = { (bf16*)(sm + 4 * MAT_BYTES),
                     (bf16*)(sm + 4 * MAT_BYTES + 2 * HALF_BYTES) };
    bf16* WGL[2] = { (bf16*)(sm + 4 * MAT_BYTES + HALF_BYTES),
                     (bf16*)(sm + 4 * MAT_BYTES + 3 * HALF_BYTES) };

    const int tid  = threadIdx.x;
    const int wid  = tid >> 5, lane = tid & 31;
    const int grp  = tid >> 8;            // 0 or 1 (warps 0-7 / 8-15)
    const int tg   = tid & 255;           // thread id within group
    const int row0 = blockIdx.x * 128;
    const int t    = blockIdx.y;

    const bf16* A1hG = aggmh + (size_t)t * NC;
    const bf16* A1lG = aggml + (size_t)t * NC;
    const bf16* A2hG = a2hb + (size_t)t * a2stride;
    const bf16* A2lG = a2lb + (size_t)t * a2stride;
    const bf16* BIH = ffh + (size_t)t * 3 * FW;
    const bf16* BIL = ffl + (size_t)t * 3 * FW;
    const bf16* BHH = whhhb + (size_t)t * FW;
    const bf16* BHL = whhlb + (size_t)t * FW;
    const float* bih = bihb + t * G3;
    const float* bhh = bhhb + t * G3;
    bf16* mho = mh_out + (size_t)t * NC;
    bf16* mlo = ml_out + (size_t)t * NC;

    const uint32_t uA1H = smem_u32(A1H), uA1L = smem_u32(A1L);
    const uint32_t uA2H = smem_u32(A2H), uA2L = smem_u32(A2L);
    const uint32_t uWH  = smem_u32(WGH[grp]), uWL = smem_u32(WGL[grp]);
    const int barid = 1 + grp;

#define STAGE_W(srcH_, srcL_, blk_) do { \
    for (int i_ = 0; i_ < 4; i_++) { \
        int g_ = tg + i_ * 256; \
        int n_ = g_ >> 4, k8_ = (g_ & 15) * 8; \
        size_t o_ = (size_t)((blk_) * 128 + grp * 64 + n_) * C + k8_; \
        uint32_t so_ = (uint32_t)((n_ * TS + k8_) * 2); \
        CP_ASYNC16(uWH + so_, (srcH_) + o_); \
        CP_ASYNC16(uWL + so_, (srcL_) + o_); \
    } \
    CP_COMMIT(); \
} while (0)

    STAGE_W(BIH, BIL, 0);

#pragma unroll
    for (int i = 0; i < 4; i++) {
        int g = tid + i * 512;
        int r = g >> 4, k8 = (g & 15) * 8;
        uint4 v1h = make_uint4(0,0,0,0), v1l = v1h, v2h = v1h, v2l = v1h;
        if (row0 + r < N_NODES) {
            size_t o = (size_t)(row0 + r) * C + k8;
            v1h = *(const uint4*)(A1hG + o);
            v1l = *(const uint4*)(A1lG + o);
            v2h = *(const uint4*)(A2hG + o);
            v2l = *(const uint4*)(A2lG + o);
        }
        int so = r * TS + k8;
        *(uint4*)(A1H + so) = v1h;
        *(uint4*)(A1L + so) = v1l;
        *(uint4*)(A2H + so) = v2h;
        *(uint4*)(A2L + so) = v2l;
    }
    CP_WAIT0();
    __syncthreads();

    const int m0 = (wid & 3) * 32;
    const int n0 = ((wid >> 2) & 1) * 32;

    float rg[2][4][4], zg[2][4][4];

#pragma unroll
    for (int blk = 0; blk < 3; blk++) {
        float acc_i[2][4][4], acc_h[2][4][4];
        gemm_tile32(uA1H, uA1L, uWH, uWL, m0, n0, lane, acc_i);
        BARG(barid);
        STAGE_W(BHH, BHL, blk);
        CP_WAIT0();
        BARG(barid);
        gemm_tile32(uA2H, uA2L, uWH, uWL, m0, n0, lane, acc_h);
        BARG(barid);
        if (blk < 2) STAGE_W(BIH, BIL, blk + 1);

        if (blk == 0 || blk == 1) {
#pragma unroll
            for (int mi = 0; mi < 2; mi++)
#pragma unroll
                for (int nj = 0; nj < 4; nj++) {
                    int c = blk * 128 + grp * 64 + n0 + nj * 8 + (lane & 3) * 2;
                    float bi0 = bih[c], bi1 = bih[c + 1];
                    float bh0 = bhh[c], bh1 = bhh[c + 1];
#pragma unroll
                    for (int q = 0; q < 4; q++) {
                        float pre = acc_i[mi][nj][q] + ((q & 1) ? bi1 : bi0)
                                  + acc_h[mi][nj][q] + ((q & 1) ? bh1 : bh0);
                        float gv = 1.f / (1.f + __expf(-pre));
                        if (blk == 0) rg[mi][nj][q] = gv;
                        else          zg[mi][nj][q] = gv;
                    }
                }
        } else {
#pragma unroll
            for (int mi = 0; mi < 2; mi++)
#pragma unroll
                for (int nj = 0; nj < 4; nj++) {
                    int mc = grp * 64 + n0 + nj * 8 + (lane & 3) * 2;
                    int c = 256 + mc;
                    float bi0 = bih[c], bi1 = bih[c + 1];
                    float bh0 = bhh[c], bh1 = bhh[c + 1];
                    float o2[4];
#pragma unroll
                    for (int q = 0; q < 4; q++) {
                        int rl = m0 + mi * 16 + (lane >> 2) + (q >> 1) * 8;
                        int cc = mc + (q & 1);
                        float pi = acc_i[mi][nj][q] + ((q & 1) ? bi1 : bi0);
                        float phv = acc_h[mi][nj][q] + ((q & 1) ? bh1 : bh0);
                        float n = tanhf(pi + rg[mi][nj][q] * phv);
                        float z = zg[mi][nj][q];
                        float mv = __bfloat162float(A2H[rl * TS + cc])
                                 + __bfloat162float(A2L[rl * TS + cc]);
                        o2[q] = (1.f - z) * n + z * mv;
                    }
#pragma unroll
                    for (int h2 = 0; h2 < 2; h2++) {
                        int gr = row0 + m0 + mi * 16 + (lane >> 2) + h2 * 8;
                        if (gr >= N_NODES) continue;
                        float v0 = o2[h2 * 2], v1 = o2[h2 * 2 + 1];
                        bf16 h0, l0, h1, l1;
                        split1(v0, h0, l0); split1(v1, h1, l1);
                        bf162 ph2; ph2.x = h0; ph2.y = h1;
                        bf162 pl2; pl2.x = l0; pl2.y = l1;
                        size_t go = (size_t)gr * C + mc;
                        *(bf162*)(mho + go) = ph2;
                        *(bf162*)(mlo + go) = pl2;
                    }
                }
        }
        if (blk < 2) {
            CP_WAIT0();
            BARG(barid);
        }
    }
#undef STAGE_W
}

// ---------------- F = conv_w @ wih^T -----------------------------------------
__global__ void __launch_bounds__(256, 1)
k_fuse(const bf16* __restrict__ cwh, const bf16* __restrict__ cwl,
       const bf16* __restrict__ wihh, const bf16* __restrict__ wihl,
       float* __restrict__ F) {
    extern __shared__ char sm[];
    bf16* AH = (bf16*)(sm);
    bf16* AL = (bf16*)(sm + MAT_BYTES);
    bf16* BH = (bf16*)(sm + 2 * MAT_BYTES);
    bf16* BL = (bf16*)(sm + 3 * MAT_BYTES);

    const int tid  = threadIdx.x;
    const int col0 = blockIdx.x * 128;
    const int w    = blockIdx.y;
    const int bt   = w / 3;
    const bf16* Ah = cwh + (size_t)w * CW;
    const bf16* Al = cwl + (size_t)w * CW;
    const bf16* Wh = wihh + (size_t)bt * FW + (size_t)col0 * C;
    const bf16* Wl = wihl + (size_t)bt * FW + (size_t)col0 * C;
    float* Y = F + (size_t)w * FW;

#pragma unroll
    for (int i = 0; i < 8; i++) {
        int g = tid + i * 256;
        int r = g >> 4, k8 = (g & 15) * 8;
        *(uint4*)(AH + r * TS + k8) = *(const uint4*)(Ah + (size_t)r * C + k8);
        *(uint4*)(AL + r * TS + k8) = *(const uint4*)(Al + (size_t)r * C + k8);
        *(uint4*)(BH + r * TS + k8) = *(const uint4*)(Wh + (size_t)r * C + k8);
        *(uint4*)(BL + r * TS + k8) = *(const uint4*)(Wl + (size_t)r * C + k8);
    }
    __syncthreads();

    const int wid  = tid >> 5, lane = tid & 31;
    const int m0 = (wid & 3) * 32;
    const int n0 = (wid >> 2) * 64;
    const int arow = lane & 15;
    const int acol = (lane >> 4) << 3;
    const int brow = (lane & 7) + ((lane >> 4) << 3);
    const int bcol = ((lane >> 3) & 1) << 3;
    const uint32_t uAH = smem_u32(AH), uAL = smem_u32(AL);
    const uint32_t uBH = smem_u32(BH), uBL = smem_u32(BL);

    float acc[2][8][4];
#pragma unroll
    for (int mi = 0; mi < 2; mi++)
#pragma unroll
        for (int nj = 0; nj < 8; nj++)
#pragma unroll
            for (int q = 0; q < 4; q++) acc[mi][nj][q] = 0.f;

#pragma unroll
    for (int ks = 0; ks < 8; ks++) {
        const int k = ks * 16;
        uint32_t ah[2][4], al[2][4];
#pragma unroll
        for (int mi = 0; mi < 2; mi++) {
            uint32_t off = (uint32_t)(((m0 + mi * 16 + arow) * TS + k + acol) * 2);
            LDSM4(ah[mi], uAH + off);
            LDSM4(al[mi], uAL + off);
        }
        uint32_t bh[8][2], bl[8][2];
#pragma unroll
        for (int nq = 0; nq < 4; nq++) {
            uint32_t off = (uint32_t)(((n0 + nq * 16 + brow) * TS + k + bcol) * 2);
            uint32_t r4[4];
            LDSM4(r4, uBH + off);
            bh[2*nq][0]=r4[0]; bh[2*nq][1]=r4[1]; bh[2*nq+1][0]=r4[2]; bh[2*nq+1][1]=r4[3];
            LDSM4(r4, uBL + off);
            bl[2*nq][0]=r4[0]; bl[2*nq][1]=r4[1]; bl[2*nq+1][0]=r4[2]; bl[2*nq+1][1]=r4[3];
        }
#pragma unroll
        for (int mi = 0; mi < 2; mi++)
#pragma unroll
            for (int nj = 0; nj < 8; nj++) {
                MMA(acc[mi][nj], ah[mi], bh[nj]);
                MMA(acc[mi][nj], ah[mi], bl[nj]);
                MMA(acc[mi][nj], al[mi], bh[nj]);
            }
    }

    const int rbase = m0 + (lane >> 2);
    const int cbase = n0 + (lane & 3) * 2;
#pragma unroll
    for (int mi = 0; mi < 2; mi++)
#pragma unroll
        for (int nj = 0; nj < 8; nj++) {
            int gr = rbase + mi * 16;
            int gc = col0 + cbase + nj * 8;
            *(float2*)(Y + (size_t)gr * G3 + gc) =
                make_float2(acc[mi][nj][0], acc[mi][nj][1]);
            *(float2*)(Y + (size_t)(gr + 8) * G3 + gc) =
                make_float2(acc[mi][nj][2], acc[mi][nj][3]);
        }
}

// F [w][k][n] -> Ff [w][n][k] hi/lo
__global__ void k_cvt_trF(const float* __restrict__ F, bf16* __restrict__ oh,
                          bf16* __restrict__ ol) {
    int idx = blockIdx.x * 256 + threadIdx.x;
    if (idx >= 18 * FW) return;
    int w = idx / FW, r = idx % FW;
    int n = r >> 7, k = r & 127;
    float v = F[(size_t)w * FW + (size_t)k * G3 + n];
    bf16 h, l; split1(v, h, l);
    oh[idx] = h; ol[idx] = l;
}

// ---------------- fused weight split (all weight tensors, one launch) --------
__global__ void k_cvtall(const float* __restrict__ cw, const float* __restrict__ wih,
                         const float* __restrict__ whh, const float* __restrict__ w1,
                         bf16* __restrict__ cwh, bf16* __restrict__ cwl,
                         bf16* __restrict__ wihh, bf16* __restrict__ wihl,
                         bf16* __restrict__ whhh, bf16* __restrict__ whhl,
                         bf16* __restrict__ w1h, bf16* __restrict__ w1l) {
    int i = blockIdx.x * 256 + threadIdx.x;
    const int n1 = 18 * CW;
    const int n2 = 6 * G3 * C;
    bf16 h, l;
    if (i < n1) {
        split1(cw[i], h, l); cwh[i] = h; cwl[i] = l; return;
    }
    i -= n1;
    if (i < n2) {
        split1(wih[i], h, l); wihh[i] = h; wihl[i] = l; return;
    }
    i -= n2;
    if (i < n2) {
        split1(whh[i], h, l); whhh[i] = h; whhl[i] = l; return;
    }
    i -= n2;
    if (i < CW) {
        split1(w1[i], h, l); w1h[i] = h; w1l[i] = l;
    }
}

// ---------------- CSR build --------------------------------------------------
__global__ void k_izero2(int* __restrict__ a, int* __restrict__ b, int n) {
    int i = blockIdx.x * 256 + threadIdx.x;
    if (i < n) { a[i] = 0; b[i] = 0; }
}
__global__ void k_count(const int* __restrict__ ei, const int* __restrict__ et,
                        int* __restrict__ cnt) {
    int e = blockIdx.x * 256 + threadIdx.x;
    if (e >= N_EDGES) return;
    atomicAdd(cnt + et[e] * N_NODES + ei[N_EDGES + e], 1);
}
__global__ void k_scan1(const int* __restrict__ cnt, int* __restrict__ incl,
                        int* __restrict__ bsum) {
    __shared__ int sm[1024];
    int i = blockIdx.x * 1024 + threadIdx.x;
    int v = (i < M3) ? cnt[i] : 0;
    sm[threadIdx.x] = v;
    __syncthreads();
#pragma unroll
    for (int off = 1; off < 1024; off <<= 1) {
        int t = (threadIdx.x >= off) ? sm[threadIdx.x - off] : 0;
        __syncthreads();
        sm[threadIdx.x] += t;
        __syncthreads();
    }
    if (i < M3) incl[i] = sm[threadIdx.x];
    if (threadIdx.x == 1023) bsum[blockIdx.x] = sm[1023];
}
// parallel exclusive scan of block sums (nb <= 256)
__global__ void k_scan2(int* __restrict__ bsum, int nb) {
    __shared__ int sm2[256];
    int i = threadIdx.x;
    int v = (i < nb) ? bsum[i] : 0;
    sm2[i] = v;
    __syncthreads();
#pragma unroll
    for (int off = 1; off < 256; off <<= 1) {
        int t = (i >= off) ? sm2[i - off] : 0;
        __syncthreads();
        sm2[i] += t;
        __syncthreads();
    }
    if (i < nb) bsum[i] = sm2[i] - v;   // exclusive prefix
}
__global__ void k_scan3(const int* __restrict__ incl, const int* __restrict__ bsum,
                        int* __restrict__ indptr) {
    int i = blockIdx.x * 1024 + threadIdx.x;
    if (i < M3) indptr[i + 1] = incl[i] + bsum[blockIdx.x];
    if (i == 0) indptr[0] = 0;
}
// fill using indptr base + zeroed per-bucket counter
__global__ void k_fill(const int* __restrict__ ei, const int* __restrict__ et,
                       const int* __restrict__ indptr, int* __restrict__ cur,
                       int* __restrict__ eidx) {
    int e = blockIdx.x * 256 + threadIdx.x;
    if (e >= N_EDGES) return;
    int tn = et[e] * N_NODES + ei[N_EDGES + e];
    int p = indptr[tn] + atomicAdd(cur + tn, 1);
    eidx[p] = ei[e];
}

// ---------------- gather: 16 lanes/node, 2 nodes/warp, pairwise ILP ----------
__global__ void k_gather3(const bf16* __restrict__ srch, const bf16* __restrict__ srcl,
                          int sstride,
                          const int* __restrict__ eidx, const int* __restrict__ indptr,
                          bf16* __restrict__ aggh, bf16* __restrict__ aggl) {
    int warp = blockIdx.x * 8 + (threadIdx.x >> 5);
    int node = warp * 2 + ((threadIdx.x >> 4) & 1);
    int lane16 = threadIdx.x & 15;
    int t = blockIdx.y;
    if (node >= N_NODES) return;
    const bf16* mh = srch + (size_t)t * sstride;
    const bf16* ml = srcl + (size_t)t * sstride;
    int tn = t * N_NODES + node;
    int beg = indptr[tn], end = indptr[tn + 1];
    float a[8];
#pragma unroll
    for (int q = 0; q < 8; q++) a[q] = 0.f;
    const int co = lane16 * 8;
    int j = beg;
    for (; j + 2 <= end; j += 2) {
        int i0 = eidx[j], i1 = eidx[j + 1];
        size_t o0 = (size_t)i0 * C + co;
        size_t o1 = (size_t)i1 * C + co;
        uint4 h0 = *(const uint4*)(mh + o0);
        uint4 l0 = *(const uint4*)(ml + o0);
        uint4 h1 = *(const uint4*)(mh + o1);
        uint4 l1 = *(const uint4*)(ml + o1);
        acc8(a, h0, l0);
        acc8(a, h1, l1);
    }
    if (j < end) {
        size_t o = (size_t)eidx[j] * C + co;
        acc8(a, *(const uint4*)(mh + o), *(const uint4*)(ml + o));
    }
    // split & pack 8 channels -> uint4 hi, uint4 lo
    unsigned hs[8], ls[8];
#pragma unroll
    for (int q = 0; q < 8; q++) {
        bf16 h, l; split1(a[q], h, l);
        hs[q] = (unsigned)__bfloat16_as_ushort(h);
        ls[q] = (unsigned)__bfloat16_as_ushort(l);
    }
    uint4 oh, ol;
    oh.x = hs[0] | (hs[1] << 16); oh.y = hs[2] | (hs[3] << 16);
    oh.z = hs[4] | (hs[5] << 16); oh.w = hs[6] | (hs[7] << 16);
    ol.x = ls[0] | (ls[1] << 16); ol.y = ls[2] | (ls[3] << 16);
    ol.z = ls[4] | (ls[5] << 16); ol.w = ls[6] | (ls[7] << 16);
    size_t o = (size_t)t * NC + (size_t)node * C + co;
    *(uint4*)(aggh + o) = oh;
    *(uint4*)(aggl + o) = ol;
}

// ---------------- head GEMM (128-row tile) -----------------------------------
__global__ void __launch_bounds__(256, 1)
k_mma2(const bf16* __restrict__ Ah, const bf16* __restrict__ Al,
       const bf16* __restrict__ Wh, const bf16* __restrict__ Wl,
       const float* __restrict__ bias, float* __restrict__ Y) {
    extern __shared__ char sm[];
    bf16* AH = (bf16*)(sm);
    bf16* AL = (bf16*)(sm + MAT_BYTES);
    bf16* BH = (bf16*)(sm + 2 * MAT_BYTES);
    bf16* BL = (bf16*)(sm + 3 * MAT_BYTES);

    const int tid  = threadIdx.x;
    const int row0 = blockIdx.x * 128;

#pragma unroll
    for (int i = 0; i < 8; i++) {
        int g = tid + i * 256;
        int r = g >> 4, k8 = (g & 15) * 8;
        uint4 vh = make_uint4(0u, 0u, 0u, 0u), vl = vh;
        if (row0 + r < N_NODES) {
            vh = *(const uint4*)(Ah + (size_t)(row0 + r) * C + k8);
            vl = *(const uint4*)(Al + (size_t)(row0 + r) * C + k8);
        }
        *(uint4*)(AH + r * TS + k8) = vh;
        *(uint4*)(AL + r * TS + k8) = vl;
        *(uint4*)(BH + r * TS + k8) = *(const uint4*)(Wh + (size_t)r * C + k8);
        *(uint4*)(BL + r * TS + k8) = *(const uint4*)(Wl + (size_t)r * C + k8);
    }
    __syncthreads();

    const int wid  = tid >> 5, lane = tid & 31;
    const int m0 = (wid & 3) * 32;
    const int n0 = (wid >> 2) * 64;
    const int arow = lane & 15;
    const int acol = (lane >> 4) << 3;
    const int brow = (lane & 7) + ((lane >> 4) << 3);
    const int bcol = ((lane >> 3) & 1) << 3;
    const uint32_t uAH = smem_u32(AH), uAL = smem_u32(AL);
    const uint32_t uBH = smem_u32(BH), uBL = smem_u32(BL);

    float acc[2][8][4];
#pragma unroll
    for (int mi = 0; mi < 2; mi++)
#pragma unroll
        for (int nj = 0; nj < 8; nj++)
#pragma unroll
            for (int q = 0; q < 4; q++) acc[mi][nj][q] = 0.f;

#pragma unroll
    for (int ks = 0; ks < 8; ks++) {
        const int k = ks * 16;
        uint32_t ah[2][4], al[2][4];
#pragma unroll
        for (int mi = 0; mi < 2; mi++) {
            uint32_t off = (uint32_t)(((m0 + mi * 16 + arow) * TS + k + acol) * 2);
            LDSM4(ah[mi], uAH + off);
            LDSM4(al[mi], uAL + off);
        }
        uint32_t bh[8][2], bl[8][2];
#pragma unroll
        for (int nq = 0; nq < 4; nq++) {
            uint32_t off = (uint32_t)(((n0 + nq * 16 + brow) * TS + k + bcol) * 2);
            uint32_t r4[4];
            LDSM4(r4, uBH + off);
            bh[2*nq][0]=r4[0]; bh[2*nq][1]=r4[1]; bh[2*nq+1][0]=r4[2]; bh[2*nq+1][1]=r4[3];
            LDSM4(r4, uBL + off);
            bl[2*nq][0]=r4[0]; bl[2*nq][1]=r4[1]; bl[2*nq+1][0]=r4[2]; bl[2*nq+1][1]=r4[3];
        }
#pragma unroll
        for (int mi = 0; mi < 2; mi++)
#pragma unroll
            for (int nj = 0; nj < 8; nj++) {
                MMA(acc[mi][nj], ah[mi], bh[nj]);
                MMA(acc[mi][nj], ah[mi], bl[nj]);
                MMA(acc[mi][nj], al[mi], bh[nj]);
            }
    }

    const int rbase = row0 + m0 + (lane >> 2);
    const int cbase = n0 + (lane & 3) * 2;
#pragma unroll
    for (int mi = 0; mi < 2; mi++)
#pragma unroll
        for (int nj = 0; nj < 8; nj++) {
            int gr = rbase + mi * 16;
            int gc = cbase + nj * 8;
            float b0 = bias[gc], b1 = bias[gc + 1];
            float2 v0, v1;
            v0.x = fmaxf(acc[mi][nj][0] + b0, 0.f);
            v0.y = fmaxf(acc[mi][nj][1] + b1, 0.f);
            v1.x = fmaxf(acc[mi][nj][2] + b0, 0.f);
            v1.y = fmaxf(acc[mi][nj][3] + b1, 0.f);
            if (gr < N_NODES)
                *(float2*)(Y + (size_t)gr * C + gc) = v0;
            if (gr + 8 < N_NODES)
                *(float2*)(Y + (size_t)(gr + 8) * C + gc) = v1;
        }
}

// ---------------- feature build ----------------------------------------------
__global__ void k_feat(const int* __restrict__ xt, const int* __restrict__ xk,
                       const float* __restrict__ xs, float* __restrict__ h,
                       bf16* __restrict__ hh, bf16* __restrict__ hl) {
    int i = blockIdx.x;
    int c = threadIdx.x;
    int t = xt[i];
    int k = xk[i];
    k = min(max(k, 0), 93);
    float v;
    if (c < 32)       v = (c == t) ? 1.f : 0.f;
    else if (c < 126) v = ((c - 32) == k) ? 1.f : 0.f;
    else              v = xs[i * 2 + (c - 126)];
    size_t o = (size_t)i * C + c;
    h[o] = v;
    bf16 bh, bl; split1(v, bh, bl);
    hh[o] = bh; hl[o] = bl;
}

// ---------------- LayerNorm(h + sum_t m_t)*g+b, ReLU -------------------------
__global__ void k_ln(float* __restrict__ h, const bf16* __restrict__ mh,
                     const bf16* __restrict__ ml,
                     const float* __restrict__ g, const float* __restrict__ b,
                     bf16* __restrict__ hh, bf16* __restrict__ hl) {
    int i = blockIdx.x * 8 + (threadIdx.x >> 5);
    int lane = threadIdx.x & 31;
    if (i >= N_NODES) return;
    size_t o4 = (size_t)i * C + lane * 4;
    float4 v = ((float4*)(h + (size_t)i * C))[lane];
#pragma unroll
    for (int t = 0; t < 3; t++) {
        size_t o = (size_t)t * NC + o4;
        uint2 uh = *(const uint2*)(mh + o);
        uint2 ul = *(const uint2*)(ml + o);
        float4 tmp = make_float4(0.f, 0.f, 0.f, 0.f);
        acc4(tmp, uh, ul);
        v.x += tmp.x; v.y += tmp.y; v.z += tmp.z; v.w += tmp.w;
    }
    float s  = v.x + v.y + v.z + v.w;
    float ss = v.x * v.x + v.y * v.y + v.z * v.z + v.w * v.w;
#pragma unroll
    for (int off = 16; off; off >>= 1) {
        s  += __shfl_xor_sync(0xffffffffu, s, off);
        ss += __shfl_xor_sync(0xffffffffu, ss, off);
    }
    float mu  = s * (1.f / 128.f);
    float var = ss * (1.f / 128.f) - mu * mu;
    float inv = rsqrtf(var + 1e-5f);
    float4 gg = ((const float4*)g)[lane];
    float4 bb = ((const float4*)b)[lane];
    float4 o;
    o.x = fmaxf((v.x - mu) * inv * gg.x + bb.x, 0.f);
    o.y = fmaxf((v.y - mu) * inv * gg.y + bb.y, 0.f);
    o.z = fmaxf((v.z - mu) * inv * gg.z + bb.z, 0.f);
    o.w = fmaxf((v.w - mu) * inv * gg.w + bb.w, 0.f);
    ((float4*)(h + (size_t)i * C))[lane] = o;
    bf16 hx, lx, hy, ly, hz, lz, hw, lw;
    split1(o.x, hx, lx); split1(o.y, hy, ly);
    split1(o.z, hz, lz); split1(o.w, hw, lw);
    bf162 p01, p23, q01, q23;
    p01.x = hx; p01.y = hy; p23.x = hz; p23.y = hw;
    q01.x = lx; q01.y = ly; q23.x = lz; q23.y = lw;
    *(bf162*)(hh + o4)     = p01;
    *(bf162*)(hh + o4 + 2) = p23;
    *(bf162*)(hl + o4)     = q01;
    *(bf162*)(hl + o4 + 2) = q23;
}

// ---------------- head second layer ------------------------------------------
__global__ void k_head2(const float* __restrict__ z, const float* __restrict__ w2,
                        const float* __restrict__ b2, float* __restrict__ out) {
    int i = blockIdx.x * 8 + (threadIdx.x >> 5);
    int lane = threadIdx.x & 31;
    if (i >= N_NODES) return;
    float4 zv = ((const float4*)(z + (size_t)i * C))[lane];
    float4 w0 = ((const float4*)w2)[lane];
    float4 w1 = ((const float4*)(w2 + C))[lane];
    float d0 = zv.x * w0.x + zv.y * w0.y + zv.z * w0.z + zv.w * w0.w;
    float d1 = zv.x * w1.x + zv.y * w1.y + zv.z * w1.z + zv.w * w1.w;
#pragma unroll
    for (int off = 16; off; off >>= 1) {
        d0 += __shfl_xor_sync(0xffffffffu, d0, off);
        d1 += __shfl_xor_sync(0xffffffffu, d1, off);
    }
    if (lane == 0) {
        out[(size_t)i * 2 + 0] = d0 + b2[0];
        out[(size_t)i * 2 + 1] = d1 + b2[1];
    }
}

// ---------------- driver -----------------------------------------------------
extern "C" void kernel_launch(void* const* d_in, const int* in_sizes, int n_in,
                              void* d_out, int out_size) {
    const int*   x_type     = (const int*)d_in[0];
    const int*   x_tok      = (const int*)d_in[1];
    const float* x_small    = (const float*)d_in[2];
    const int*   edge_index = (const int*)d_in[3];
    const int*   edge_type  = (const int*)d_in[4];
    const float* conv_w     = (const float*)d_in[5];
    const float* gru_wih    = (const float*)d_in[6];
    const float* gru_whh    = (const float*)d_in[7];
    const float* gru_bih    = (const float*)d_in[8];
    const float* gru_bhh    = (const float*)d_in[9];
    const float* ln_g       = (const float*)d_in[10];
    const float* ln_b       = (const float*)d_in[11];
    const float* head_w1    = (const float*)d_in[12];
    const float* head_b1    = (const float*)d_in[13];
    const float* head_w2    = (const float*)d_in[14];
    const float* head_b2    = (const float*)d_in[15];
    float* out = (float*)d_out;

    float *ph, *px, *pF;
    bf16 *phh, *phl, *pmh, *pml, *pah, *pal;
    bf16 *pcwh, *pcwl, *pwihh, *pwihl, *pwhhh, *pwhhl, *pw1h, *pw1l, *pffh, *pffl;
    int *pcnt, *pincl, *pcur, *pbsum, *pindptr, *peidx;
    cudaGetSymbolAddress((void**)&ph,   g_h);
    cudaGetSymbolAddress((void**)&px,   g_x);
    cudaGetSymbolAddress((void**)&pF,   g_F);
    cudaGetSymbolAddress((void**)&phh,  g_hh);
    cudaGetSymbolAddress((void**)&phl,  g_hl);
    cudaGetSymbolAddress((void**)&pmh,  g_mh);
    cudaGetSymbolAddress((void**)&pml,  g_ml);
    cudaGetSymbolAddress((void**)&pah,  g_ah);
    cudaGetSymbolAddress((void**)&pal,  g_al);
    cudaGetSymbolAddress((void**)&pcwh, g_cwh);
    cudaGetSymbolAddress((void**)&pcwl, g_cwl);
    cudaGetSymbolAddress((void**)&pwihh, g_wihh);
    cudaGetSymbolAddress((void**)&pwihl, g_wihl);
    cudaGetSymbolAddress((void**)&pwhhh, g_whhh);
    cudaGetSymbolAddress((void**)&pwhhl, g_whhl);
    cudaGetSymbolAddress((void**)&pw1h, g_w1h);
    cudaGetSymbolAddress((void**)&pw1l, g_w1l);
    cudaGetSymbolAddress((void**)&pffh, g_ffh);
    cudaGetSymbolAddress((void**)&pffl, g_ffl);
    cudaGetSymbolAddress((void**)&pcnt, g_cnt);
    cudaGetSymbolAddress((void**)&pincl, g_incl);
    cudaGetSymbolAddress((void**)&pcur, g_cur);
    cudaGetSymbolAddress((void**)&pbsum, g_bsum);
    cudaGetSymbolAddress((void**)&pindptr, g_indptr);
    cudaGetSymbolAddress((void**)&peidx, g_eidx);

    const int SMEMSZ = 4 * MAT_BYTES;                     // 139264 (k_fuse, head)
    const int GSMEM  = 6 * MAT_BYTES;                     // 208896 (gates)
    cudaFuncSetAttribute(k_fuse,
                         cudaFuncAttributeMaxDynamicSharedMemorySize, SMEMSZ);
    cudaFuncSetAttribute(k_mma2,
                         cudaFuncAttributeMaxDynamicSharedMemorySize, SMEMSZ);
    cudaFuncSetAttribute(k_gates_b,
                         cudaFuncAttributeMaxDynamicSharedMemorySize, GSMEM);

    const int rowBlocks = (N_NODES + 127) / 128;    // 391
    const int warpGrid = (N_NODES + 7) / 8;
    const int gatherGrid = (N_NODES + 15) / 16;     // 3125 (2 nodes/warp)
    const int SCANB = (M3 + 1023) / 1024;           // 147
    const int EG = (N_EDGES + 255) / 256;
    const int CVTN = 18 * CW + 2 * 6 * G3 * C + CW; // 901120

    // ---- one-time: features, weight splits, CSR, fused weights ----
    k_feat<<<N_NODES, 128>>>(x_type, x_tok, x_small, ph, phh, phl);
    k_cvtall<<<(CVTN + 255) / 256, 256>>>(conv_w, gru_wih, gru_whh, head_w1,
                                          pcwh, pcwl, pwihh, pwihl,
                                          pwhhh, pwhhl, pw1h, pw1l);

    k_izero2<<<(M3 + 255)/256, 256>>>(pcnt, pcur, M3);
    k_count<<<EG, 256>>>(edge_index, edge_type, pcnt);
    k_scan1<<<SCANB, 1024>>>(pcnt, pincl, pbsum);
    k_scan2<<<1, 256>>>(pbsum, SCANB);
    k_scan3<<<SCANB, 1024>>>(pincl, pbsum, pindptr);
    k_fill<<<EG, 256>>>(edge_index, edge_type, pindptr, pcur, peidx);

    k_fuse<<<dim3(3, 18), 256, SMEMSZ>>>(pcwh, pcwl, pwihh, pwihl, pF);
    k_cvt_trF<<<(18*FW + 255)/256, 256>>>(pF, pffh, pffl);

    for (int b = 0; b < 2; b++) {
        for (int s = 0; s < 3; s++) {
            const bf16* srch = (s == 0) ? phh : pmh;
            const bf16* srcl = (s == 0) ? phl : pml;
            int stride = (s == 0) ? 0 : NC;
            k_gather3<<<dim3(gatherGrid, 3), 256>>>(srch, srcl, stride,
                                                    peidx, pindptr, pah, pal);
            k_gates_b<<<dim3(rowBlocks, 3), 512, GSMEM>>>(
                pah, pal, srch, srcl, stride,
                pffh + (size_t)(b * 9 + s) * FW, pffl + (size_t)(b * 9 + s) * FW,
                pwhhh + (size_t)b * 3 * FW, pwhhl + (size_t)b * 3 * FW,
                gru_bih + (size_t)b * 3 * G3, gru_bhh + (size_t)b * 3 * G3,
                pmh, pml);
        }
        k_ln<<<warpGrid, 256>>>(ph, pmh, pml, ln_g + b * C, ln_b + b * C, phh, phl);
    }

    // head
    k_mma2<<<rowBlocks, 256, SMEMSZ>>>(phh, phl, pw1h, pw1l, head_b1, px);
    k_head2<<<warpGrid, 256>>>(px, head_w2, head_b2, out);
}

// round 17
// speedup vs baseline: 1.0366x; 1.0008x over previous
#include <cuda_runtime.h>
#include <cuda_bf16.h>
#include <math.h>
#include <stdint.h>

#define N_NODES 50000
#define N_EDGES 500000
#define C 128
#define G3 384
#define NC (N_NODES*C)
#define M3 (3*N_NODES)
#define FW (C*G3)            // 49152 per fused weight
#define CW (C*C)             // 16384 per conv weight

typedef __nv_bfloat16 bf16;
typedef __nv_bfloat162 bf162;

// ---------------- scratch (device globals) -----------------------------------
__device__ float g_h[NC];
__device__ bf16  g_hh[NC], g_hl[NC];
__device__ bf16  g_mh[3*NC], g_ml[3*NC];     // per-type GRU state
__device__ bf16  g_ah[3*NC], g_al[3*NC];     // per-type gathered m
// weights
__device__ bf16  g_cwh[18*CW], g_cwl[18*CW];
__device__ bf16  g_wihh[6*G3*C], g_wihl[6*G3*C];
__device__ bf16  g_whhh[6*G3*C], g_whhl[6*G3*C];
__device__ bf16  g_w1h[CW], g_w1l[CW];
__device__ float g_F[18*FW];
__device__ bf16  g_ffh[18*FW], g_ffl[18*FW];
// CSR
__device__ int g_cnt[M3], g_incl[M3], g_cur[M3], g_bsum[256];
__device__ int g_indptr[M3+1];
__device__ int g_eidx[N_EDGES];

// ---------------- helpers ----------------------------------------------------
__device__ __forceinline__ uint32_t smem_u32(const void* p) {
    uint32_t a;
    asm("{ .reg .u64 t; cvta.to.shared.u64 t, %1; cvt.u32.u64 %0, t; }"
        : "=r"(a) : "l"(p));
    return a;
}

#define LDSM4(r, addr) \
    asm volatile("ldmatrix.sync.aligned.m8n8.x4.shared.b16 {%0,%1,%2,%3}, [%4];" \
        : "=r"((r)[0]), "=r"((r)[1]), "=r"((r)[2]), "=r"((r)[3]) : "r"(addr))

#define MMA(d, a, b) \
    asm volatile("mma.sync.aligned.m16n8k16.row.col.f32.bf16.bf16.f32 " \
        "{%0,%1,%2,%3}, {%4,%5,%6,%7}, {%8,%9}, {%0,%1,%2,%3};" \
        : "+f"((d)[0]), "+f"((d)[1]), "+f"((d)[2]), "+f"((d)[3]) \
        : "r"((a)[0]), "r"((a)[1]), "r"((a)[2]), "r"((a)[3]), \
          "r"((b)[0]), "r"((b)[1]))

#define CP_ASYNC16(saddr, gptr) \
    asm volatile("cp.async.cg.shared.global [%0], [%1], 16;" \
        :: "r"(saddr), "l"(gptr))
#define CP_COMMIT() asm volatile("cp.async.commit_group;" ::: "memory")
#define CP_WAIT0()  asm volatile("cp.async.wait_group 0;" ::: "memory")
#define BARG(id)    asm volatile("bar.sync %0, 256;" :: "r"(id) : "memory")

__device__ __forceinline__ void split1(float v, bf16& h, bf16& l) {
    h = __float2bfloat16(v);
    l = __float2bfloat16(v - __bfloat162float(h));
}

__device__ __forceinline__ void acc4(float4& s, uint2 uh, uint2 ul) {
    float2 a = __bfloat1622float2(*(bf162*)&uh.x);
    float2 b = __bfloat1622float2(*(bf162*)&uh.y);
    float2 c = __bfloat1622float2(*(bf162*)&ul.x);
    float2 d = __bfloat1622float2(*(bf162*)&ul.y);
    s.x += a.x + c.x; s.y += a.y + c.y;
    s.z += b.x + d.x; s.w += b.y + d.y;
}

// accumulate 8 channels (uint4 = 8 bf16) hi+lo into fp32
__device__ __forceinline__ void acc8(float* a, uint4 vh, uint4 vl) {
    float2 p;
    p = __bfloat1622float2(*(bf162*)&vh.x); a[0] += p.x; a[1] += p.y;
    p = __bfloat1622float2(*(bf162*)&vh.y); a[2] += p.x; a[3] += p.y;
    p = __bfloat1622float2(*(bf162*)&vh.z); a[4] += p.x; a[5] += p.y;
    p = __bfloat1622float2(*(bf162*)&vh.w); a[6] += p.x; a[7] += p.y;
    p = __bfloat1622float2(*(bf162*)&vl.x); a[0] += p.x; a[1] += p.y;
    p = __bfloat1622float2(*(bf162*)&vl.y); a[2] += p.x; a[3] += p.y;
    p = __bfloat1622float2(*(bf162*)&vl.z); a[4] += p.x; a[5] += p.y;
    p = __bfloat1622float2(*(bf162*)&vl.w); a[6] += p.x; a[7] += p.y;
}

#define TS 136
#define MAT_BYTES (128 * TS * 2)   // 34816
#define HALF_BYTES (64 * TS * 2)   // 17408

// 32m x 32n warp-tile GEMM; B buffer holds 64 n-rows (n0 in {0,32}).
__device__ __forceinline__ void gemm_tile32(uint32_t uAH, uint32_t uAL,
                                            uint32_t uBH, uint32_t uBL,
                                            int m0, int n0, int lane,
                                            float acc[2][4][4]) {
#pragma unroll
    for (int mi = 0; mi < 2; mi++)
#pragma unroll
        for (int nj = 0; nj < 4; nj++)
#pragma unroll
            for (int q = 0; q < 4; q++) acc[mi][nj][q] = 0.f;

    const int arow = lane & 15;
    const int acol = (lane >> 4) << 3;
    const int brow = (lane & 7) + ((lane >> 4) << 3);
    const int bcol = ((lane >> 3) & 1) << 3;

#pragma unroll
    for (int ks = 0; ks < 8; ks++) {
        const int k = ks * 16;
        uint32_t ah[2][4], al[2][4];
#pragma unroll
        for (int mi = 0; mi < 2; mi++) {
            uint32_t off = (uint32_t)(((m0 + mi * 16 + arow) * TS + k + acol) * 2);
            LDSM4(ah[mi], uAH + off);
            LDSM4(al[mi], uAL + off);
        }
        uint32_t bh[4][2], bl[4][2];
#pragma unroll
        for (int nq = 0; nq < 2; nq++) {
            uint32_t off = (uint32_t)(((n0 + nq * 16 + brow) * TS + k + bcol) * 2);
            uint32_t r4[4];
            LDSM4(r4, uBH + off);
            bh[2*nq][0]=r4[0]; bh[2*nq][1]=r4[1]; bh[2*nq+1][0]=r4[2]; bh[2*nq+1][1]=r4[3];
            LDSM4(r4, uBL + off);
            bl[2*nq][0]=r4[0]; bl[2*nq][1]=r4[1]; bl[2*nq+1][0]=r4[2]; bl[2*nq+1][1]=r4[3];
        }
#pragma unroll
        for (int mi = 0; mi < 2; mi++)
#pragma unroll
            for (int nj = 0; nj < 4; nj++) {
                MMA(acc[mi][nj], ah[mi], bh[nj]);
                MMA(acc[mi][nj], ah[mi], bl[nj]);
                MMA(acc[mi][nj], al[mi], bh[nj]);
            }
    }
}

// ---------------- gi/gh GEMM + GRU: 128-row tile, 512 threads ----------------
// Two independent 8-warp groups (named barriers): group g owns output columns
// [64g, 64g+64) of each 128-col block, with its own half-width W buffers.
// SMEM: A1h|A1l|A2h|A2l (4x34816) | W halves (4x17408) = 208896 B.
__global__ void __launch_bounds__(512, 1)
k_gates_b(const bf16* __restrict__ aggmh, const bf16* __restrict__ aggml,
          const bf16* __restrict__ a2hb,  const bf16* __restrict__ a2lb,
          int a2stride,
          const bf16* __restrict__ ffh, const bf16* __restrict__ ffl,
          const bf16* __restrict__ whhhb, const bf16* __restrict__ whhlb,
          const float* __restrict__ bihb, const float* __restrict__ bhhb,
          bf16* __restrict__ mh_out, bf16* __restrict__ ml_out) {
    extern __shared__ char sm[];
    bf16* A1H = (bf16*)(sm);
    bf16* A1L = (bf16*)(sm + MAT_BYTES);
    bf16* A2H = (bf16*)(sm + 2 * MAT_BYTES);
    bf16* A2L = (bf16*)(sm + 3 * MAT_BYTES);
    bf16* WGH[2] = { (bf16*)(sm + 4 * MAT_BYTES),
                     (bf16*)(sm + 4 * MAT_BYTES + 2 * HALF_BYTES) };
    bf16* WGL[2] = { (bf16*)(sm + 4 * MAT_BYTES + HALF_BYTES),
                     (bf16*)(sm + 4 * MAT_BYTES + 3 * HALF_BYTES) };

    const int tid  = threadIdx.x;
    const int wid  = tid >> 5, lane = tid & 31;
    const int grp  = tid >> 8;            // 0 or 1 (warps 0-7 / 8-15)
    const int tg   = tid & 255;           // thread id within group
    const int row0 = blockIdx.x * 128;
    const int t    = blockIdx.y;

    const bf16* A1hG = aggmh + (size_t)t * NC;
    const bf16* A1lG = aggml + (size_t)t * NC;
    const bf16* A2hG = a2hb + (size_t)t * a2stride;
    const bf16* A2lG = a2lb + (size_t)t * a2stride;
    const bf16* BIH = ffh + (size_t)t * 3 * FW;
    const bf16* BIL = ffl + (size_t)t * 3 * FW;
    const bf16* BHH = whhhb + (size_t)t * FW;
    const bf16* BHL = whhlb + (size_t)t * FW;
    const float* bih = bihb + t * G3;
    const float* bhh = bhhb + t * G3;
    bf16* mho = mh_out + (size_t)t * NC;
    bf16* mlo = ml_out + (size_t)t * NC;

    const uint32_t uA1H = smem_u32(A1H), uA1L = smem_u32(A1L);
    const uint32_t uA2H = smem_u32(A2H), uA2L = smem_u32(A2L);
    const uint32_t uWH  = smem_u32(WGH[grp]), uWL = smem_u32(WGL[grp]);
    const int barid = 1 + grp;

#define STAGE_W(srcH_, srcL_, blk_) do { \
    for (int i_ = 0; i_ < 4; i_++) { \
        int g_ = tg + i_ * 256; \
        int n_ = g_ >> 4, k8_ = (g_ & 15) * 8; \
        size_t o_ = (size_t)((blk_) * 128 + grp * 64 + n_) * C + k8_; \
        uint32_t so_ = (uint32_t)((n_ * TS + k8_) * 2); \
        CP_ASYNC16(uWH + so_, (srcH_) + o_); \
        CP_ASYNC16(uWL + so_, (srcL_) + o_); \
    } \
    CP_COMMIT(); \
} while (0)

    STAGE_W(BIH, BIL, 0);

#pragma unroll
    for (int i = 0; i < 4; i++) {
        int g = tid + i * 512;
        int r = g >> 4, k8 = (g & 15) * 8;
        uint4 v1h = make_uint4(0,0,0,0), v1l = v1h, v2h = v1h, v2l = v1h;
        if (row0 + r < N_NODES) {
            size_t o = (size_t)(row0 + r) * C + k8;
            v1h = *(const uint4*)(A1hG + o);
            v1l = *(const uint4*)(A1lG + o);
            v2h = *(const uint4*)(A2hG + o);
            v2l = *(const uint4*)(A2lG + o);
        }
        int so = r * TS + k8;
        *(uint4*)(A1H + so) = v1h;
        *(uint4*)(A1L + so) = v1l;
        *(uint4*)(A2H + so) = v2h;
        *(uint4*)(A2L + so) = v2l;
    }
    CP_WAIT0();
    __syncthreads();

    const int m0 = (wid & 3) * 32;
    const int n0 = ((wid >> 2) & 1) * 32;

    float rg[2][4][4], zg[2][4][4];

#pragma unroll
    for (int blk = 0; blk < 3; blk++) {
        float acc_i[2][4][4], acc_h[2][4][4];
        gemm_tile32(uA1H, uA1L, uWH, uWL, m0, n0, lane, acc_i);
        BARG(barid);
        STAGE_W(BHH, BHL, blk);
        CP_WAIT0();
        BARG(barid);
        gemm_tile32(uA2H, uA2L, uWH, uWL, m0, n0, lane, acc_h);
        BARG(barid);
        if (blk < 2) STAGE_W(BIH, BIL, blk + 1);

        if (blk == 0 || blk == 1) {
#pragma unroll
            for (int mi = 0; mi < 2; mi++)
#pragma unroll
                for (int nj = 0; nj < 4; nj++) {
                    int c = blk * 128 + grp * 64 + n0 + nj * 8 + (lane & 3) * 2;
                    float bi0 = bih[c], bi1 = bih[c + 1];
                    float bh0 = bhh[c], bh1 = bhh[c + 1];
#pragma unroll
                    for (int q = 0; q < 4; q++) {
                        float pre = acc_i[mi][nj][q] + ((q & 1) ? bi1 : bi0)
                                  + acc_h[mi][nj][q] + ((q & 1) ? bh1 : bh0);
                        float gv = 1.f / (1.f + __expf(-pre));
                        if (blk == 0) rg[mi][nj][q] = gv;
                        else          zg[mi][nj][q] = gv;
                    }
                }
        } else {
#pragma unroll
            for (int mi = 0; mi < 2; mi++)
#pragma unroll
                for (int nj = 0; nj < 4; nj++) {
                    int mc = grp * 64 + n0 + nj * 8 + (lane & 3) * 2;
                    int c = 256 + mc;
                    float bi0 = bih[c], bi1 = bih[c + 1];
                    float bh0 = bhh[c], bh1 = bhh[c + 1];
                    float o2[4];
#pragma unroll
                    for (int q = 0; q < 4; q++) {
                        int rl = m0 + mi * 16 + (lane >> 2) + (q >> 1) * 8;
                        int cc = mc + (q & 1);
                        float pi = acc_i[mi][nj][q] + ((q & 1) ? bi1 : bi0);
                        float phv = acc_h[mi][nj][q] + ((q & 1) ? bh1 : bh0);
                        float n = tanhf(pi + rg[mi][nj][q] * phv);
                        float z = zg[mi][nj][q];
                        float mv = __bfloat162float(A2H[rl * TS + cc])
                                 + __bfloat162float(A2L[rl * TS + cc]);
                        o2[q] = (1.f - z) * n + z * mv;
                    }
#pragma unroll
                    for (int h2 = 0; h2 < 2; h2++) {
                        int gr = row0 + m0 + mi * 16 + (lane >> 2) + h2 * 8;
                        if (gr >= N_NODES) continue;
                        float v0 = o2[h2 * 2], v1 = o2[h2 * 2 + 1];
                        bf16 h0, l0, h1, l1;
                        split1(v0, h0, l0); split1(v1, h1, l1);
                        bf162 ph2; ph2.x = h0; ph2.y = h1;
                        bf162 pl2; pl2.x = l0; pl2.y = l1;
                        size_t go = (size_t)gr * C + mc;
                        *(bf162*)(mho + go) = ph2;
                        *(bf162*)(mlo + go) = pl2;
                    }
                }
        }
        if (blk < 2) {
            CP_WAIT0();
            BARG(barid);
        }
    }
#undef STAGE_W
}

// ---------------- F = conv_w @ wih^T -----------------------------------------
__global__ void __launch_bounds__(256, 1)
k_fuse(const bf16* __restrict__ cwh, const bf16* __restrict__ cwl,
       const bf16* __restrict__ wihh, const bf16* __restrict__ wihl,
       float* __restrict__ F) {
    extern __shared__ char sm[];
    bf16* AH = (bf16*)(sm);
    bf16* AL = (bf16*)(sm + MAT_BYTES);
    bf16* BH = (bf16*)(sm + 2 * MAT_BYTES);
    bf16* BL = (bf16*)(sm + 3 * MAT_BYTES);

    const int tid  = threadIdx.x;
    const int col0 = blockIdx.x * 128;
    const int w    = blockIdx.y;
    const int bt   = w / 3;
    const bf16* Ah = cwh + (size_t)w * CW;
    const bf16* Al = cwl + (size_t)w * CW;
    const bf16* Wh = wihh + (size_t)bt * FW + (size_t)col0 * C;
    const bf16* Wl = wihl + (size_t)bt * FW + (size_t)col0 * C;
    float* Y = F + (size_t)w * FW;

#pragma unroll
    for (int i = 0; i < 8; i++) {
        int g = tid + i * 256;
        int r = g >> 4, k8 = (g & 15) * 8;
        *(uint4*)(AH + r * TS + k8) = *(const uint4*)(Ah + (size_t)r * C + k8);
        *(uint4*)(AL + r * TS + k8) = *(const uint4*)(Al + (size_t)r * C + k8);
        *(uint4*)(BH + r * TS + k8) = *(const uint4*)(Wh + (size_t)r * C + k8);
        *(uint4*)(BL + r * TS + k8) = *(const uint4*)(Wl + (size_t)r * C + k8);
    }
    __syncthreads();

    const int wid  = tid >> 5, lane = tid & 31;
    const int m0 = (wid & 3) * 32;
    const int n0 = (wid >> 2) * 64;
    const int arow = lane & 15;
    const int acol = (lane >> 4) << 3;
    const int brow = (lane & 7) + ((lane >> 4) << 3);
    const int bcol = ((lane >> 3) & 1) << 3;
    const uint32_t uAH = smem_u32(AH), uAL = smem_u32(AL);
    const uint32_t uBH = smem_u32(BH), uBL = smem_u32(BL);

    float acc[2][8][4];
#pragma unroll
    for (int mi = 0; mi < 2; mi++)
#pragma unroll
        for (int nj = 0; nj < 8; nj++)
#pragma unroll
            for (int q = 0; q < 4; q++) acc[mi][nj][q] = 0.f;

#pragma unroll
    for (int ks = 0; ks < 8; ks++) {
        const int k = ks * 16;
        uint32_t ah[2][4], al[2][4];
#pragma unroll
        for (int mi = 0; mi < 2; mi++) {
            uint32_t off = (uint32_t)(((m0 + mi * 16 + arow) * TS + k + acol) * 2);
            LDSM4(ah[mi], uAH + off);
            LDSM4(al[mi], uAL + off);
        }
        uint32_t bh[8][2], bl[8][2];
#pragma unroll
        for (int nq = 0; nq < 4; nq++) {
            uint32_t off = (uint32_t)(((n0 + nq * 16 + brow) * TS + k + bcol) * 2);
            uint32_t r4[4];
            LDSM4(r4, uBH + off);
            bh[2*nq][0]=r4[0]; bh[2*nq][1]=r4[1]; bh[2*nq+1][0]=r4[2]; bh[2*nq+1][1]=r4[3];
            LDSM4(r4, uBL + off);
            bl[2*nq][0]=r4[0]; bl[2*nq][1]=r4[1]; bl[2*nq+1][0]=r4[2]; bl[2*nq+1][1]=r4[3];
        }
#pragma unroll
        for (int mi = 0; mi < 2; mi++)
#pragma unroll
            for (int nj = 0; nj < 8; nj++) {
                MMA(acc[mi][nj], ah[mi], bh[nj]);
                MMA(acc[mi][nj], ah[mi], bl[nj]);
                MMA(acc[mi][nj], al[mi], bh[nj]);
            }
    }

    const int rbase = m0 + (lane >> 2);
    const int cbase = n0 + (lane & 3) * 2;
#pragma unroll
    for (int mi = 0; mi < 2; mi++)
#pragma unroll
        for (int nj = 0; nj < 8; nj++) {
            int gr = rbase + mi * 16;
            int gc = col0 + cbase + nj * 8;
            *(float2*)(Y + (size_t)gr * G3 + gc) =
                make_float2(acc[mi][nj][0], acc[mi][nj][1]);
            *(float2*)(Y + (size_t)(gr + 8) * G3 + gc) =
                make_float2(acc[mi][nj][2], acc[mi][nj][3]);
        }
}

// F [w][k][n] -> Ff [w][n][k] hi/lo
__global__ void k_cvt_trF(const float* __restrict__ F, bf16* __restrict__ oh,
                          bf16* __restrict__ ol) {
    int idx = blockIdx.x * 256 + threadIdx.x;
    if (idx >= 18 * FW) return;
    int w = idx / FW, r = idx % FW;
    int n = r >> 7, k = r & 127;
    float v = F[(size_t)w * FW + (size_t)k * G3 + n];
    bf16 h, l; split1(v, h, l);
    oh[idx] = h; ol[idx] = l;
}

// ---------------- fused weight split (all weight tensors, one launch) --------
__global__ void k_cvtall(const float* __restrict__ cw, const float* __restrict__ wih,
                         const float* __restrict__ whh, const float* __restrict__ w1,
                         bf16* __restrict__ cwh, bf16* __restrict__ cwl,
                         bf16* __restrict__ wihh, bf16* __restrict__ wihl,
                         bf16* __restrict__ whhh, bf16* __restrict__ whhl,
                         bf16* __restrict__ w1h, bf16* __restrict__ w1l) {
    int i = blockIdx.x * 256 + threadIdx.x;
    const int n1 = 18 * CW;
    const int n2 = 6 * G3 * C;
    bf16 h, l;
    if (i < n1) {
        split1(cw[i], h, l); cwh[i] = h; cwl[i] = l; return;
    }
    i -= n1;
    if (i < n2) {
        split1(wih[i], h, l); wihh[i] = h; wihl[i] = l; return;
    }
    i -= n2;
    if (i < n2) {
        split1(whh[i], h, l); whhh[i] = h; whhl[i] = l; return;
    }
    i -= n2;
    if (i < CW) {
        split1(w1[i], h, l); w1h[i] = h; w1l[i] = l;
    }
}

// ---------------- CSR build --------------------------------------------------
__global__ void k_izero2(int* __restrict__ a, int* __restrict__ b, int n) {
    int i = blockIdx.x * 256 + threadIdx.x;
    if (i < n) { a[i] = 0; b[i] = 0; }
}
__global__ void k_count(const int* __restrict__ ei, const int* __restrict__ et,
                        int* __restrict__ cnt) {
    int e = blockIdx.x * 256 + threadIdx.x;
    if (e >= N_EDGES) return;
    atomicAdd(cnt + et[e] * N_NODES + ei[N_EDGES + e], 1);
}
__global__ void k_scan1(const int* __restrict__ cnt, int* __restrict__ incl,
                        int* __restrict__ bsum) {
    __shared__ int sm[1024];
    int i = blockIdx.x * 1024 + threadIdx.x;
    int v = (i < M3) ? cnt[i] : 0;
    sm[threadIdx.x] = v;
    __syncthreads();
#pragma unroll
    for (int off = 1; off < 1024; off <<= 1) {
        int t = (threadIdx.x >= off) ? sm[threadIdx.x - off] : 0;
        __syncthreads();
        sm[threadIdx.x] += t;
        __syncthreads();
    }
    if (i < M3) incl[i] = sm[threadIdx.x];
    if (threadIdx.x == 1023) bsum[blockIdx.x] = sm[1023];
}
// parallel exclusive scan of block sums (nb <= 256)
__global__ void k_scan2(int* __restrict__ bsum, int nb) {
    __shared__ int sm2[256];
    int i = threadIdx.x;
    int v = (i < nb) ? bsum[i] : 0;
    sm2[i] = v;
    __syncthreads();
#pragma unroll
    for (int off = 1; off < 256; off <<= 1) {
        int t = (i >= off) ? sm2[i - off] : 0;
        __syncthreads();
        sm2[i] += t;
        __syncthreads();
    }
    if (i < nb) bsum[i] = sm2[i] - v;   // exclusive prefix
}
__global__ void k_scan3(const int* __restrict__ incl, const int* __restrict__ bsum,
                        int* __restrict__ indptr) {
    int i = blockIdx.x * 1024 + threadIdx.x;
    if (i < M3) indptr[i + 1] = incl[i] + bsum[blockIdx.x];
    if (i == 0) indptr[0] = 0;
}
// fill using indptr base + zeroed per-bucket counter
__global__ void k_fill(const int* __restrict__ ei, const int* __restrict__ et,
                       const int* __restrict__ indptr, int* __restrict__ cur,
                       int* __restrict__ eidx) {
    int e = blockIdx.x * 256 + threadIdx.x;
    if (e >= N_EDGES) return;
    int tn = et[e] * N_NODES + ei[N_EDGES + e];
    int p = indptr[tn] + atomicAdd(cur + tn, 1);
    eidx[p] = ei[e];
}

// ---------------- gather: 16 lanes/node, 2 nodes/warp, pairwise ILP ----------
__global__ void k_gather3(const bf16* __restrict__ srch, const bf16* __restrict__ srcl,
                          int sstride,
                          const int* __restrict__ eidx, const int* __restrict__ indptr,
                          bf16* __restrict__ aggh, bf16* __restrict__ aggl) {
    int warp = blockIdx.x * 8 + (threadIdx.x >> 5);
    int node = warp * 2 + ((threadIdx.x >> 4) & 1);
    int lane16 = threadIdx.x & 15;
    int t = blockIdx.y;
    if (node >= N_NODES) return;
    const bf16* mh = srch + (size_t)t * sstride;
    const bf16* ml = srcl + (size_t)t * sstride;
    int tn = t * N_NODES + node;
    int beg = indptr[tn], end = indptr[tn + 1];
    float a[8];
#pragma unroll
    for (int q = 0; q < 8; q++) a[q] = 0.f;
    const int co = lane16 * 8;
    int j = beg;
    for (; j + 2 <= end; j += 2) {
        int i0 = eidx[j], i1 = eidx[j + 1];
        size_t o0 = (size_t)i0 * C + co;
        size_t o1 = (size_t)i1 * C + co;
        uint4 h0 = *(const uint4*)(mh + o0);
        uint4 l0 = *(const uint4*)(ml + o0);
        uint4 h1 = *(const uint4*)(mh + o1);
        uint4 l1 = *(const uint4*)(ml + o1);
        acc8(a, h0, l0);
        acc8(a, h1, l1);
    }
    if (j < end) {
        size_t o = (size_t)eidx[j] * C + co;
        acc8(a, *(const uint4*)(mh + o), *(const uint4*)(ml + o));
    }
    // split & pack 8 channels -> uint4 hi, uint4 lo
    unsigned hs[8], ls[8];
#pragma unroll
    for (int q = 0; q < 8; q++) {
        bf16 h, l; split1(a[q], h, l);
        hs[q] = (unsigned)__bfloat16_as_ushort(h);
        ls[q] = (unsigned)__bfloat16_as_ushort(l);
    }
    uint4 oh, ol;
    oh.x = hs[0] | (hs[1] << 16); oh.y = hs[2] | (hs[3] << 16);
    oh.z = hs[4] | (hs[5] << 16); oh.w = hs[6] | (hs[7] << 16);
    ol.x = ls[0] | (ls[1] << 16); ol.y = ls[2] | (ls[3] << 16);
    ol.z = ls[4] | (ls[5] << 16); ol.w = ls[6] | (ls[7] << 16);
    size_t o = (size_t)t * NC + (size_t)node * C + co;
    *(uint4*)(aggh + o) = oh;
    *(uint4*)(aggl + o) = ol;
}

// ---------------- fused head: out = relu(h@w1^T+b1) @ w2^T + b2 --------------
// 128-row tile; block-level reduction of the 2-col projection in smem.
__global__ void __launch_bounds__(256, 1)
k_headf(const bf16* __restrict__ Ah, const bf16* __restrict__ Al,
        const bf16* __restrict__ Wh, const bf16* __restrict__ Wl,
        const float* __restrict__ bias, const float* __restrict__ w2,
        const float* __restrict__ b2, float* __restrict__ out) {
    extern __shared__ char sm[];
    bf16* AH = (bf16*)(sm);
    bf16* AL = (bf16*)(sm + MAT_BYTES);
    bf16* BH = (bf16*)(sm + 2 * MAT_BYTES);
    bf16* BL = (bf16*)(sm + 3 * MAT_BYTES);

    const int tid  = threadIdx.x;
    const int row0 = blockIdx.x * 128;

#pragma unroll
    for (int i = 0; i < 8; i++) {
        int g = tid + i * 256;
        int r = g >> 4, k8 = (g & 15) * 8;
        uint4 vh = make_uint4(0u, 0u, 0u, 0u), vl = vh;
        if (row0 + r < N_NODES) {
            vh = *(const uint4*)(Ah + (size_t)(row0 + r) * C + k8);
            vl = *(const uint4*)(Al + (size_t)(row0 + r) * C + k8);
        }
        *(uint4*)(AH + r * TS + k8) = vh;
        *(uint4*)(AL + r * TS + k8) = vl;
        *(uint4*)(BH + r * TS + k8) = *(const uint4*)(Wh + (size_t)r * C + k8);
        *(uint4*)(BL + r * TS + k8) = *(const uint4*)(Wl + (size_t)r * C + k8);
    }
    __syncthreads();

    const int wid  = tid >> 5, lane = tid & 31;
    const int m0 = (wid & 3) * 32;
    const int n0 = (wid >> 2) * 64;
    const int arow = lane & 15;
    const int acol = (lane >> 4) << 3;
    const int brow = (lane & 7) + ((lane >> 4) << 3);
    const int bcol = ((lane >> 3) & 1) << 3;
    const uint32_t uAH = smem_u32(AH), uAL = smem_u32(AL);
    const uint32_t uBH = smem_u32(BH), uBL = smem_u32(BL);

    float acc[2][8][4];
#pragma unroll
    for (int mi = 0; mi < 2; mi++)
#pragma unroll
        for (int nj = 0; nj < 8; nj++)
#pragma unroll
            for (int q = 0; q < 4; q++) acc[mi][nj][q] = 0.f;

#pragma unroll
    for (int ks = 0; ks < 8; ks++) {
        const int k = ks * 16;
        uint32_t ah[2][4], al[2][4];
#pragma unroll
        for (int mi = 0; mi < 2; mi++) {
            uint32_t off = (uint32_t)(((m0 + mi * 16 + arow) * TS + k + acol) * 2);
            LDSM4(ah[mi], uAH + off);
            LDSM4(al[mi], uAL + off);
        }
        uint32_t bh[8][2], bl[8][2];
#pragma unroll
        for (int nq = 0; nq < 4; nq++) {
            uint32_t off = (uint32_t)(((n0 + nq * 16 + brow) * TS + k + bcol) * 2);
            uint32_t r4[4];
            LDSM4(r4, uBH + off);
            bh[2*nq][0]=r4[0]; bh[2*nq][1]=r4[1]; bh[2*nq+1][0]=r4[2]; bh[2*nq+1][1]=r4[3];
            LDSM4(r4, uBL + off);
            bl[2*nq][0]=r4[0]; bl[2*nq][1]=r4[1]; bl[2*nq+1][0]=r4[2]; bl[2*nq+1][1]=r4[3];
        }
#pragma unroll
        for (int mi = 0; mi < 2; mi++)
#pragma unroll
            for (int nj = 0; nj < 8; nj++) {
                MMA(acc[mi][nj], ah[mi], bh[nj]);
                MMA(acc[mi][nj], ah[mi], bl[nj]);
                MMA(acc[mi][nj], al[mi], bh[nj]);
            }
    }

    // ---- fused epilogue: z = relu(acc + b1); partial dot with w2 rows ----
    const int cbase = n0 + (lane & 3) * 2;
    float p[4][2];
#pragma unroll
    for (int r = 0; r < 4; r++) { p[r][0] = 0.f; p[r][1] = 0.f; }
#pragma unroll
    for (int mi = 0; mi < 2; mi++)
#pragma unroll
        for (int nj = 0; nj < 8; nj++) {
            int gc = cbase + nj * 8;
            float b0 = bias[gc], b1 = bias[gc + 1];
            float w20a = w2[gc], w20b = w2[gc + 1];
            float w21a = w2[C + gc], w21b = w2[C + gc + 1];
            float v00 = fmaxf(acc[mi][nj][0] + b0, 0.f);
            float v01 = fmaxf(acc[mi][nj][1] + b1, 0.f);
            float v10 = fmaxf(acc[mi][nj][2] + b0, 0.f);
            float v11 = fmaxf(acc[mi][nj][3] + b1, 0.f);
            p[mi * 2 + 0][0] += v00 * w20a + v01 * w20b;
            p[mi * 2 + 0][1] += v00 * w21a + v01 * w21b;
            p[mi * 2 + 1][0] += v10 * w20a + v11 * w20b;
            p[mi * 2 + 1][1] += v10 * w21a + v11 * w21b;
        }
    __syncthreads();            // done reading A/B smem; reuse as reduction buf
    float* red = (float*)sm;    // 128 rows x 2 outputs
    red[tid] = 0.f;             // blockDim == 256 covers all slots
    __syncthreads();
#pragma unroll
    for (int mi = 0; mi < 2; mi++)
#pragma unroll
        for (int h2 = 0; h2 < 2; h2++) {
            int rl = m0 + (lane >> 2) + mi * 16 + h2 * 8;
            atomicAdd(&red[rl * 2 + 0], p[mi * 2 + h2][0]);
            atomicAdd(&red[rl * 2 + 1], p[mi * 2 + h2][1]);
        }
    __syncthreads();
    {
        int row = tid >> 1, cc = tid & 1;
        int gr = row0 + row;
        if (gr < N_NODES)
            out[(size_t)gr * 2 + cc] = red[tid] + b2[cc];
    }
}

// ---------------- feature build (2 nodes/block) -------------------------------
__global__ void k_feat(const int* __restrict__ xt, const int* __restrict__ xk,
                       const float* __restrict__ xs, float* __restrict__ h,
                       bf16* __restrict__ hh, bf16* __restrict__ hl) {
    int i = blockIdx.x * 2 + (threadIdx.x >> 7);
    int c = threadIdx.x & 127;
    if (i >= N_NODES) return;
    int t = xt[i];
    int k = xk[i];
    k = min(max(k, 0), 93);
    float v;
    if (c < 32)       v = (c == t) ? 1.f : 0.f;
    else if (c < 126) v = ((c - 32) == k) ? 1.f : 0.f;
    else              v = xs[i * 2 + (c - 126)];
    size_t o = (size_t)i * C + c;
    h[o] = v;
    bf16 bh, bl; split1(v, bh, bl);
    hh[o] = bh; hl[o] = bl;
}

// ---------------- LayerNorm(h + sum_t m_t)*g+b, ReLU -------------------------
__global__ void k_ln(float* __restrict__ h, const bf16* __restrict__ mh,
                     const bf16* __restrict__ ml,
                     const float* __restrict__ g, const float* __restrict__ b,
                     bf16* __restrict__ hh, bf16* __restrict__ hl) {
    int i = blockIdx.x * 8 + (threadIdx.x >> 5);
    int lane = threadIdx.x & 31;
    if (i >= N_NODES) return;
    size_t o4 = (size_t)i * C + lane * 4;
    float4 v = ((float4*)(h + (size_t)i * C))[lane];
#pragma unroll
    for (int t = 0; t < 3; t++) {
        size_t o = (size_t)t * NC + o4;
        uint2 uh = *(const uint2*)(mh + o);
        uint2 ul = *(const uint2*)(ml + o);
        float4 tmp = make_float4(0.f, 0.f, 0.f, 0.f);
        acc4(tmp, uh, ul);
        v.x += tmp.x; v.y += tmp.y; v.z += tmp.z; v.w += tmp.w;
    }
    float s  = v.x + v.y + v.z + v.w;
    float ss = v.x * v.x + v.y * v.y + v.z * v.z + v.w * v.w;
#pragma unroll
    for (int off = 16; off; off >>= 1) {
        s  += __shfl_xor_sync(0xffffffffu, s, off);
        ss += __shfl_xor_sync(0xffffffffu, ss, off);
    }
    float mu  = s * (1.f / 128.f);
    float var = ss * (1.f / 128.f) - mu * mu;
    float inv = rsqrtf(var + 1e-5f);
    float4 gg = ((const float4*)g)[lane];
    float4 bb = ((const float4*)b)[lane];
    float4 o;
    o.x = fmaxf((v.x - mu) * inv * gg.x + bb.x, 0.f);
    o.y = fmaxf((v.y - mu) * inv * gg.y + bb.y, 0.f);
    o.z = fmaxf((v.z - mu) * inv * gg.z + bb.z, 0.f);
    o.w = fmaxf((v.w - mu) * inv * gg.w + bb.w, 0.f);
    ((float4*)(h + (size_t)i * C))[lane] = o;
    bf16 hx, lx, hy, ly, hz, lz, hw, lw;
    split1(o.x, hx, lx); split1(o.y, hy, ly);
    split1(o.z, hz, lz); split1(o.w, hw, lw);
    bf162 p01, p23, q01, q23;
    p01.x = hx; p01.y = hy; p23.x = hz; p23.y = hw;
    q01.x = lx; q01.y = ly; q23.x = lz; q23.y = lw;
    *(bf162*)(hh + o4)     = p01;
    *(bf162*)(hh + o4 + 2) = p23;
    *(bf162*)(hl + o4)     = q01;
    *(bf162*)(hl + o4 + 2) = q23;
}

// ---------------- driver -----------------------------------------------------
extern "C" void kernel_launch(void* const* d_in, const int* in_sizes, int n_in,
                              void* d_out, int out_size) {
    const int*   x_type     = (const int*)d_in[0];
    const int*   x_tok      = (const int*)d_in[1];
    const float* x_small    = (const float*)d_in[2];
    const int*   edge_index = (const int*)d_in[3];
    const int*   edge_type  = (const int*)d_in[4];
    const float* conv_w     = (const float*)d_in[5];
    const float* gru_wih    = (const float*)d_in[6];
    const float* gru_whh    = (const float*)d_in[7];
    const float* gru_bih    = (const float*)d_in[8];
    const float* gru_bhh    = (const float*)d_in[9];
    const float* ln_g       = (const float*)d_in[10];
    const float* ln_b       = (const float*)d_in[11];
    const float* head_w1    = (const float*)d_in[12];
    const float* head_b1    = (const float*)d_in[13];
    const float* head_w2    = (const float*)d_in[14];
    const float* head_b2    = (const float*)d_in[15];
    float* out = (float*)d_out;

    float *ph, *pF;
    bf16 *phh, *phl, *pmh, *pml, *pah, *pal;
    bf16 *pcwh, *pcwl, *pwihh, *pwihl, *pwhhh, *pwhhl, *pw1h, *pw1l, *pffh, *pffl;
    int *pcnt, *pincl, *pcur, *pbsum, *pindptr, *peidx;
    cudaGetSymbolAddress((void**)&ph,   g_h);
    cudaGetSymbolAddress((void**)&pF,   g_F);
    cudaGetSymbolAddress((void**)&phh,  g_hh);
    cudaGetSymbolAddress((void**)&phl,  g_hl);
    cudaGetSymbolAddress((void**)&pmh,  g_mh);
    cudaGetSymbolAddress((void**)&pml,  g_ml);
    cudaGetSymbolAddress((void**)&pah,  g_ah);
    cudaGetSymbolAddress((void**)&pal,  g_al);
    cudaGetSymbolAddress((void**)&pcwh, g_cwh);
    cudaGetSymbolAddress((void**)&pcwl, g_cwl);
    cudaGetSymbolAddress((void**)&pwihh, g_wihh);
    cudaGetSymbolAddress((void**)&pwihl, g_wihl);
    cudaGetSymbolAddress((void**)&pwhhh, g_whhh);
    cudaGetSymbolAddress((void**)&pwhhl, g_whhl);
    cudaGetSymbolAddress((void**)&pw1h, g_w1h);
    cudaGetSymbolAddress((void**)&pw1l, g_w1l);
    cudaGetSymbolAddress((void**)&pffh, g_ffh);
    cudaGetSymbolAddress((void**)&pffl, g_ffl);
    cudaGetSymbolAddress((void**)&pcnt, g_cnt);
    cudaGetSymbolAddress((void**)&pincl, g_incl);
    cudaGetSymbolAddress((void**)&pcur, g_cur);
    cudaGetSymbolAddress((void**)&pbsum, g_bsum);
    cudaGetSymbolAddress((void**)&pindptr, g_indptr);
    cudaGetSymbolAddress((void**)&peidx, g_eidx);

    const int SMEMSZ = 4 * MAT_BYTES;                     // 139264 (k_fuse, head)
    const int GSMEM  = 6 * MAT_BYTES;                     // 208896 (gates)
    cudaFuncSetAttribute(k_fuse,
                         cudaFuncAttributeMaxDynamicSharedMemorySize, SMEMSZ);
    cudaFuncSetAttribute(k_headf,
                         cudaFuncAttributeMaxDynamicSharedMemorySize, SMEMSZ);
    cudaFuncSetAttribute(k_gates_b,
                         cudaFuncAttributeMaxDynamicSharedMemorySize, GSMEM);

    const int rowBlocks = (N_NODES + 127) / 128;    // 391
    const int warpGrid = (N_NODES + 7) / 8;
    const int gatherGrid = (N_NODES + 15) / 16;     // 3125 (2 nodes/warp)
    const int SCANB = (M3 + 1023) / 1024;           // 147
    const int EG = (N_EDGES + 255) / 256;
    const int CVTN = 18 * CW + 2 * 6 * G3 * C + CW; // 901120

    // ---- one-time: features, weight splits, CSR, fused weights ----
    k_feat<<<(N_NODES + 1) / 2, 256>>>(x_type, x_tok, x_small, ph, phh, phl);
    k_cvtall<<<(CVTN + 255) / 256, 256>>>(conv_w, gru_wih, gru_whh, head_w1,
                                          pcwh, pcwl, pwihh, pwihl,
                                          pwhhh, pwhhl, pw1h, pw1l);

    k_izero2<<<(M3 + 255)/256, 256>>>(pcnt, pcur, M3);
    k_count<<<EG, 256>>>(edge_index, edge_type, pcnt);
    k_scan1<<<SCANB, 1024>>>(pcnt, pincl, pbsum);
    k_scan2<<<1, 256>>>(pbsum, SCANB);
    k_scan3<<<SCANB, 1024>>>(pincl, pbsum, pindptr);
    k_fill<<<EG, 256>>>(edge_index, edge_type, pindptr, pcur, peidx);

    k_fuse<<<dim3(3, 18), 256, SMEMSZ>>>(pcwh, pcwl, pwihh, pwihl, pF);
    k_cvt_trF<<<(18*FW + 255)/256, 256>>>(pF, pffh, pffl);

    for (int b = 0; b < 2; b++) {
        for (int s = 0; s < 3; s++) {
            const bf16* srch = (s == 0) ? phh : pmh;
            const bf16* srcl = (s == 0) ? phl : pml;
            int stride = (s == 0) ? 0 : NC;
            k_gather3<<<dim3(gatherGrid, 3), 256>>>(srch, srcl, stride,
                                                    peidx, pindptr, pah, pal);
            k_gates_b<<<dim3(rowBlocks, 3), 512, GSMEM>>>(
                pah, pal, srch, srcl, stride,
                pffh + (size_t)(b * 9 + s) * FW, pffl + (size_t)(b * 9 + s) * FW,
                pwhhh + (size_t)b * 3 * FW, pwhhl + (size_t)b * 3 * FW,
                gru_bih + (size_t)b * 3 * G3, gru_bhh + (size_t)b * 3 * G3,
                pmh, pml);
        }
        k_ln<<<warpGrid, 256>>>(ph, pmh, pml, ln_g + b * C, ln_b + b * C, phh, phl);
    }

    // fused head: GEMM + ReLU + 2-col projection + bias, straight to out
    k_headf<<<rowBlocks, 256, SMEMSZ>>>(phh, phl, pw1h, pw1l,
                                        head_b1, head_w2, head_b2, out);
}